// round 1
// baseline (speedup 1.0000x reference)
#include <cuda_runtime.h>

#define NN 50000
#define NG 1000
#define HID 64

typedef unsigned long long u64;

// ---------------- scratch (device globals; no allocations allowed) ----------
__device__ float g_t[NN * HID];      // GEMM1 output * norm_src
__device__ float g_agg1[NN * HID];   // layer0 scatter accumulator
__device__ float g_hs[NN * HID];     // relu(...)*norm_src (layer1 input)
__device__ float g_agg2[NN * HID];   // layer1 scatter accumulator
__device__ float g_deg_out[NN];
__device__ float g_deg_in[NN];
__device__ float g_norm_src[NN];
__device__ float g_norm_dst[NN];

// ---------------- packed f32x2 helpers (FFMA2) ------------------------------
__device__ __forceinline__ u64 splat2(float x) {
    u64 d; unsigned r = __float_as_uint(x);
    asm("mov.b64 %0, {%1, %1};" : "=l"(d) : "r"(r));
    return d;
}
__device__ __forceinline__ void ffma2(u64& d, u64 a, u64 b) {
    asm("fma.rn.f32x2 %0, %1, %2, %0;" : "+l"(d) : "l"(a), "l"(b));
}
__device__ __forceinline__ void unpack2(u64 d, float& lo, float& hi) {
    unsigned a, b;
    asm("mov.b64 {%0, %1}, %2;" : "=r"(a), "=r"(b) : "l"(d));
    lo = __uint_as_float(a); hi = __uint_as_float(b);
}

// ---------------- degree + norms ---------------------------------------------
__global__ void k_deg(const int* __restrict__ src, const int* __restrict__ dst, int E) {
    int e = blockIdx.x * blockDim.x + threadIdx.x;
    if (e < E) {
        atomicAdd(&g_deg_out[src[e]], 1.0f);
        atomicAdd(&g_deg_in[dst[e]], 1.0f);
    }
}

__global__ void k_norms() {
    int i = blockIdx.x * blockDim.x + threadIdx.x;
    if (i < NN) {
        g_norm_src[i] = rsqrtf(fmaxf(g_deg_out[i], 1.0f));
        g_norm_dst[i] = rsqrtf(fmaxf(g_deg_in[i], 1.0f));
    }
}

// ---------------- GEMM1: t = (concat(xu,xs) @ W0) * norm_src ----------------
// tile: 128 rows x 64 cols, K-chunks of 16, 256 threads, 8x4 micro per thread
__global__ __launch_bounds__(256) void k_gemm1(
    const float* __restrict__ xu, const float* __restrict__ xs,
    const float* __restrict__ W0) {
    __shared__ float As[16][132];   // transposed: As[k][row]
    __shared__ float Ws[16][64];

    int i0 = blockIdx.x * 128;
    int tid = threadIdx.x;
    int ty = tid >> 4, tx = tid & 15;
    int r0 = ty * 8, c0 = tx * 4;

    u64 acc[4][4] = {};   // 4 row-pairs x 4 cols

    for (int kb = 0; kb < 2 * NG; kb += 16) {
        // A tile: 128 rows x 16 k, float4 per thread x2
        #pragma unroll
        for (int it = 0; it < 2; it++) {
            int idx = it * 256 + tid;           // 0..511
            int r = idx >> 2, kq = (idx & 3) << 2;
            int i = i0 + r, kg = kb + kq;
            float4 v = make_float4(0.f, 0.f, 0.f, 0.f);
            if (i < NN)
                v = (kg < NG) ? *(const float4*)&xu[i * NG + kg]
                              : *(const float4*)&xs[i * NG + kg - NG];
            As[kq + 0][r] = v.x; As[kq + 1][r] = v.y;
            As[kq + 2][r] = v.z; As[kq + 3][r] = v.w;
        }
        // W tile: 16 x 64
        #pragma unroll
        for (int it = 0; it < 4; it++) {
            int idx = it * 256 + tid;           // 0..1023
            int kk = idx >> 6, c = idx & 63;
            Ws[kk][c] = W0[(kb + kk) * HID + c];
        }
        __syncthreads();

        #pragma unroll
        for (int kk = 0; kk < 16; kk++) {
            ulonglong2 a01 = *(const ulonglong2*)&As[kk][r0];
            ulonglong2 a23 = *(const ulonglong2*)&As[kk][r0 + 4];
            float4 wv = *(const float4*)&Ws[kk][c0];
            u64 ap[4] = {a01.x, a01.y, a23.x, a23.y};
            u64 ws0 = splat2(wv.x), ws1 = splat2(wv.y), ws2 = splat2(wv.z), ws3 = splat2(wv.w);
            #pragma unroll
            for (int rp = 0; rp < 4; rp++) {
                ffma2(acc[rp][0], ap[rp], ws0);
                ffma2(acc[rp][1], ap[rp], ws1);
                ffma2(acc[rp][2], ap[rp], ws2);
                ffma2(acc[rp][3], ap[rp], ws3);
            }
        }
        __syncthreads();
    }

    #pragma unroll
    for (int rp = 0; rp < 4; rp++) {
        float lo[4], hi[4];
        #pragma unroll
        for (int j = 0; j < 4; j++) unpack2(acc[rp][j], lo[j], hi[j]);
        int il = i0 + r0 + rp * 2;
        if (il < NN) {
            float ns = g_norm_src[il];
            float4 o = make_float4(lo[0] * ns, lo[1] * ns, lo[2] * ns, lo[3] * ns);
            *(float4*)&g_t[il * HID + c0] = o;
        }
        if (il + 1 < NN) {
            float ns = g_norm_src[il + 1];
            float4 o = make_float4(hi[0] * ns, hi[1] * ns, hi[2] * ns, hi[3] * ns);
            *(float4*)&g_t[(il + 1) * HID + c0] = o;
        }
    }
}

// ---------------- edge scatter: agg[dst] += t[src] ---------------------------
__global__ void k_scatter(const int* __restrict__ src, const int* __restrict__ dst,
                          int E, const float* __restrict__ t, float* __restrict__ agg) {
    int tid = blockIdx.x * blockDim.x + threadIdx.x;
    if (tid >= E * 16) return;
    int e = tid >> 4;
    int c4 = (tid & 15) << 2;
    int s = src[e], d = dst[e];
    float4 v = *(const float4*)&t[s * HID + c4];
    float* a = &agg[d * HID + c4];
    atomicAdd(a + 0, v.x);
    atomicAdd(a + 1, v.y);
    atomicAdd(a + 2, v.z);
    atomicAdd(a + 3, v.w);
}

// ---------------- hs = relu(agg1*norm_dst + b0) * norm_src -------------------
__global__ void k_hs(const float* __restrict__ b0) {
    int tid = blockIdx.x * blockDim.x + threadIdx.x;
    if (tid >= NN * 16) return;
    int i = tid >> 4, c4 = (tid & 15) << 2;
    float nd = g_norm_dst[i], ns = g_norm_src[i];
    float4 a = *(const float4*)&g_agg1[i * HID + c4];
    float4 b = *(const float4*)&b0[c4];
    float4 o;
    o.x = fmaxf(fmaf(a.x, nd, b.x), 0.f) * ns;
    o.y = fmaxf(fmaf(a.y, nd, b.y), 0.f) * ns;
    o.z = fmaxf(fmaf(a.z, nd, b.z), 0.f) * ns;
    o.w = fmaxf(fmaf(a.w, nd, b.w), 0.f) * ns;
    *(float4*)&g_hs[i * HID + c4] = o;
}

// ---------------- fused GEMM2 + epilogue --------------------------------------
// z = agg2*norm_dst; out[i,g] = (z.W1[:,g]+b1[g])*xu[i,g] + (z.W1[:,g+1000]+b1[g+1000])*xs[i,g]
// tile: 128 rows x 64 g (each g has beta+gamma), 256 threads, 8 rows x 4 g per thread
__global__ __launch_bounds__(256) void k_out(
    const float* __restrict__ xu, const float* __restrict__ xs,
    const float* __restrict__ W1, const float* __restrict__ b1,
    float* __restrict__ out) {
    extern __shared__ float sm[];
    float* zT = sm;               // [64][132] transposed, padded
    float* Wb = sm + 64 * 132;    // [64][64]
    float* Wg = Wb + 64 * 64;     // [64][64]

    int i0 = blockIdx.y * 128;
    int g0 = blockIdx.x * 64;
    int tid = threadIdx.x;

    // z tile (scaled by norm_dst), transposed
    #pragma unroll
    for (int it = 0; it < 32; it++) {
        int idx = it * 256 + tid;             // 0..8191
        int r = idx >> 6, k = idx & 63;
        int i = i0 + r;
        float v = 0.f;
        if (i < NN) v = g_agg2[i * HID + k] * g_norm_dst[i];
        zT[k * 132 + r] = v;
    }
    // W tiles (beta + gamma halves)
    #pragma unroll
    for (int it = 0; it < 16; it++) {
        int idx = it * 256 + tid;             // 0..4095
        int k = idx >> 6, c = idx & 63;
        int g = g0 + c;
        float wb = 0.f, wg = 0.f;
        if (g < NG) { wb = W1[k * 2 * NG + g]; wg = W1[k * 2 * NG + NG + g]; }
        Wb[k * 64 + c] = wb;
        Wg[k * 64 + c] = wg;
    }
    __syncthreads();

    int ty = tid >> 4, tx = tid & 15;
    int r0 = ty * 8, cg = tx * 4;

    u64 aB[4][4] = {}, aG[4][4] = {};
    #pragma unroll 16
    for (int k = 0; k < HID; k++) {
        ulonglong2 a01 = *(const ulonglong2*)&zT[k * 132 + r0];
        ulonglong2 a23 = *(const ulonglong2*)&zT[k * 132 + r0 + 4];
        float4 wb = *(const float4*)&Wb[k * 64 + cg];
        float4 wg = *(const float4*)&Wg[k * 64 + cg];
        u64 ap[4] = {a01.x, a01.y, a23.x, a23.y};
        u64 wbs[4] = {splat2(wb.x), splat2(wb.y), splat2(wb.z), splat2(wb.w)};
        u64 wgs[4] = {splat2(wg.x), splat2(wg.y), splat2(wg.z), splat2(wg.w)};
        #pragma unroll
        for (int rp = 0; rp < 4; rp++) {
            #pragma unroll
            for (int j = 0; j < 4; j++) {
                ffma2(aB[rp][j], ap[rp], wbs[j]);
                ffma2(aG[rp][j], ap[rp], wgs[j]);
            }
        }
    }

    int g = g0 + cg;
    if (g < NG) {
        float4 bb = *(const float4*)&b1[g];
        float4 bg = *(const float4*)&b1[NG + g];
        float bbv[4] = {bb.x, bb.y, bb.z, bb.w};
        float bgv[4] = {bg.x, bg.y, bg.z, bg.w};
        #pragma unroll
        for (int rp = 0; rp < 4; rp++) {
            float bl[4], bh[4], gl[4], gh[4];
            #pragma unroll
            for (int j = 0; j < 4; j++) {
                unpack2(aB[rp][j], bl[j], bh[j]);
                unpack2(aG[rp][j], gl[j], gh[j]);
            }
            int il = i0 + r0 + rp * 2;
            if (il < NN) {
                float4 u = *(const float4*)&xu[il * NG + g];
                float4 s = *(const float4*)&xs[il * NG + g];
                float4 o;
                o.x = (bl[0] + bbv[0]) * u.x + (gl[0] + bgv[0]) * s.x;
                o.y = (bl[1] + bbv[1]) * u.y + (gl[1] + bgv[1]) * s.y;
                o.z = (bl[2] + bbv[2]) * u.z + (gl[2] + bgv[2]) * s.z;
                o.w = (bl[3] + bbv[3]) * u.w + (gl[3] + bgv[3]) * s.w;
                *(float4*)&out[il * NG + g] = o;
            }
            if (il + 1 < NN) {
                float4 u = *(const float4*)&xu[(il + 1) * NG + g];
                float4 s = *(const float4*)&xs[(il + 1) * NG + g];
                float4 o;
                o.x = (bh[0] + bbv[0]) * u.x + (gh[0] + bgv[0]) * s.x;
                o.y = (bh[1] + bbv[1]) * u.y + (gh[1] + bgv[1]) * s.y;
                o.z = (bh[2] + bbv[2]) * u.z + (gh[2] + bgv[2]) * s.z;
                o.w = (bh[3] + bbv[3]) * u.w + (gh[3] + bgv[3]) * s.w;
                *(float4*)&out[(il + 1) * NG + g] = o;
            }
        }
    }
}

// ---------------- host launcher -----------------------------------------------
extern "C" void kernel_launch(void* const* d_in, const int* in_sizes, int n_in,
                              void* d_out, int out_size) {
    const float* xu = (const float*)d_in[0];
    const float* xs = (const float*)d_in[1];
    const float* W0 = (const float*)d_in[2];
    const float* b0 = (const float*)d_in[3];
    const float* W1 = (const float*)d_in[4];
    const float* b1 = (const float*)d_in[5];
    const int* src = (const int*)d_in[6];
    const int* dst = (const int*)d_in[7];
    int E = in_sizes[6];
    float* out = (float*)d_out;

    void *p_dego, *p_degi, *p_agg1, *p_agg2, *p_t, *p_hs;
    cudaGetSymbolAddress(&p_dego, g_deg_out);
    cudaGetSymbolAddress(&p_degi, g_deg_in);
    cudaGetSymbolAddress(&p_agg1, g_agg1);
    cudaGetSymbolAddress(&p_agg2, g_agg2);
    cudaGetSymbolAddress(&p_t, g_t);
    cudaGetSymbolAddress(&p_hs, g_hs);

    cudaMemsetAsync(p_dego, 0, NN * sizeof(float), 0);
    cudaMemsetAsync(p_degi, 0, NN * sizeof(float), 0);
    cudaMemsetAsync(p_agg1, 0, (size_t)NN * HID * sizeof(float), 0);
    cudaMemsetAsync(p_agg2, 0, (size_t)NN * HID * sizeof(float), 0);

    k_deg<<<(E + 255) / 256, 256>>>(src, dst, E);
    k_norms<<<(NN + 255) / 256, 256>>>();
    k_gemm1<<<(NN + 127) / 128, 256>>>(xu, xs, W0);
    k_scatter<<<(E * 16 + 255) / 256, 256>>>(src, dst, E, (const float*)p_t, (float*)p_agg1);
    k_hs<<<(NN * 16 + 255) / 256, 256>>>(b0);
    k_scatter<<<(E * 16 + 255) / 256, 256>>>(src, dst, E, (const float*)p_hs, (float*)p_agg2);

    cudaFuncSetAttribute(k_out, cudaFuncAttributeMaxDynamicSharedMemorySize,
                         (64 * 132 + 2 * 64 * 64) * sizeof(float));
    k_out<<<dim3(16, (NN + 127) / 128), 256, (64 * 132 + 2 * 64 * 64) * sizeof(float)>>>(
        xu, xs, W1, b1, out);
}

// round 2
// speedup vs baseline: 1.3625x; 1.3625x over previous
#include <cuda_runtime.h>

#define NN 50000
#define NG 1000
#define HID 64

typedef unsigned long long u64;

// ---------------- scratch (device globals; no allocations allowed) ----------
__device__ float g_t[NN * HID];      // GEMM1 output * norm_src
__device__ float g_agg1[NN * HID];   // layer0 scatter accumulator
__device__ float g_hs[NN * HID];     // relu(...)*norm_src (layer1 input)
__device__ float g_agg2[NN * HID];   // layer1 scatter accumulator
__device__ float g_deg_out[NN];
__device__ float g_deg_in[NN];
__device__ float g_norm_src[NN];
__device__ float g_norm_dst[NN];

// ---------------- packed f32x2 helpers (FFMA2) ------------------------------
__device__ __forceinline__ u64 splat2(float x) {
    u64 d; unsigned r = __float_as_uint(x);
    asm("mov.b64 %0, {%1, %1};" : "=l"(d) : "r"(r));
    return d;
}
__device__ __forceinline__ void ffma2(u64& d, u64 a, u64 b) {
    asm("fma.rn.f32x2 %0, %1, %2, %0;" : "+l"(d) : "l"(a), "l"(b));
}
__device__ __forceinline__ void unpack2(u64 d, float& lo, float& hi) {
    unsigned a, b;
    asm("mov.b64 {%0, %1}, %2;" : "=r"(a), "=r"(b) : "l"(d));
    lo = __uint_as_float(a); hi = __uint_as_float(b);
}

// ---------------- degree + norms ---------------------------------------------
__global__ void k_deg(const int* __restrict__ src, const int* __restrict__ dst, int E) {
    int e4 = (blockIdx.x * blockDim.x + threadIdx.x) * 4;
    if (e4 + 3 < E) {
        int4 s = *(const int4*)&src[e4];
        int4 d = *(const int4*)&dst[e4];
        atomicAdd(&g_deg_out[s.x], 1.0f);
        atomicAdd(&g_deg_out[s.y], 1.0f);
        atomicAdd(&g_deg_out[s.z], 1.0f);
        atomicAdd(&g_deg_out[s.w], 1.0f);
        atomicAdd(&g_deg_in[d.x], 1.0f);
        atomicAdd(&g_deg_in[d.y], 1.0f);
        atomicAdd(&g_deg_in[d.z], 1.0f);
        atomicAdd(&g_deg_in[d.w], 1.0f);
    } else {
        for (int e = e4; e < E; e++) {
            atomicAdd(&g_deg_out[src[e]], 1.0f);
            atomicAdd(&g_deg_in[dst[e]], 1.0f);
        }
    }
}

__global__ void k_norms() {
    int i = blockIdx.x * blockDim.x + threadIdx.x;
    if (i < NN) {
        g_norm_src[i] = rsqrtf(fmaxf(g_deg_out[i], 1.0f));
        g_norm_dst[i] = rsqrtf(fmaxf(g_deg_in[i], 1.0f));
    }
}

// ---------------- GEMM1: t = (concat(xu,xs) @ W0) * norm_src ----------------
// tile: 128 rows x 64 cols, K-chunks of 16, 256 threads, 8x4 micro per thread
__global__ __launch_bounds__(256) void k_gemm1(
    const float* __restrict__ xu, const float* __restrict__ xs,
    const float* __restrict__ W0) {
    __shared__ float As[16][132];   // transposed: As[k][row]
    __shared__ float Ws[16][64];

    int i0 = blockIdx.x * 128;
    int tid = threadIdx.x;
    int ty = tid >> 4, tx = tid & 15;
    int r0 = ty * 8, c0 = tx * 4;

    u64 acc[4][4] = {};   // 4 row-pairs x 4 cols

    for (int kb = 0; kb < 2 * NG; kb += 16) {
        // A tile: 128 rows x 16 k, float4 per thread x2
        #pragma unroll
        for (int it = 0; it < 2; it++) {
            int idx = it * 256 + tid;           // 0..511
            int r = idx >> 2, kq = (idx & 3) << 2;
            int i = i0 + r, kg = kb + kq;
            float4 v = make_float4(0.f, 0.f, 0.f, 0.f);
            if (i < NN)
                v = (kg < NG) ? *(const float4*)&xu[i * NG + kg]
                              : *(const float4*)&xs[i * NG + kg - NG];
            As[kq + 0][r] = v.x; As[kq + 1][r] = v.y;
            As[kq + 2][r] = v.z; As[kq + 3][r] = v.w;
        }
        // W tile: 16 x 64, one float4 per thread (256 threads x 4 = 1024 floats)
        {
            int kk = tid >> 4, c4 = (tid & 15) << 2;
            float4 w = *(const float4*)&W0[(kb + kk) * HID + c4];
            *(float4*)&Ws[kk][c4] = w;
        }
        __syncthreads();

        #pragma unroll
        for (int kk = 0; kk < 16; kk++) {
            ulonglong2 a01 = *(const ulonglong2*)&As[kk][r0];
            ulonglong2 a23 = *(const ulonglong2*)&As[kk][r0 + 4];
            float4 wv = *(const float4*)&Ws[kk][c0];
            u64 ap[4] = {a01.x, a01.y, a23.x, a23.y};
            u64 ws0 = splat2(wv.x), ws1 = splat2(wv.y), ws2 = splat2(wv.z), ws3 = splat2(wv.w);
            #pragma unroll
            for (int rp = 0; rp < 4; rp++) {
                ffma2(acc[rp][0], ap[rp], ws0);
                ffma2(acc[rp][1], ap[rp], ws1);
                ffma2(acc[rp][2], ap[rp], ws2);
                ffma2(acc[rp][3], ap[rp], ws3);
            }
        }
        __syncthreads();
    }

    #pragma unroll
    for (int rp = 0; rp < 4; rp++) {
        float lo[4], hi[4];
        #pragma unroll
        for (int j = 0; j < 4; j++) unpack2(acc[rp][j], lo[j], hi[j]);
        int il = i0 + r0 + rp * 2;
        if (il < NN) {
            float ns = g_norm_src[il];
            float4 o = make_float4(lo[0] * ns, lo[1] * ns, lo[2] * ns, lo[3] * ns);
            *(float4*)&g_t[il * HID + c0] = o;
        }
        if (il + 1 < NN) {
            float ns = g_norm_src[il + 1];
            float4 o = make_float4(hi[0] * ns, hi[1] * ns, hi[2] * ns, hi[3] * ns);
            *(float4*)&g_t[(il + 1) * HID + c0] = o;
        }
    }
}

// ---------------- edge scatter: agg[dst] += t[src], vector RED ----------------
__global__ void k_scatter(const int* __restrict__ src, const int* __restrict__ dst,
                          int E, const float* __restrict__ t, float* __restrict__ agg) {
    long long tid = (long long)blockIdx.x * blockDim.x + threadIdx.x;
    if (tid >= (long long)E * 16) return;
    int e = (int)(tid >> 4);
    int c4 = ((int)tid & 15) << 2;
    int s = src[e], d = dst[e];
    float4 v = *(const float4*)&t[s * HID + c4];
    asm volatile("red.global.add.v4.f32 [%0], {%1, %2, %3, %4};"
                 :: "l"(&agg[d * HID + c4]),
                    "f"(v.x), "f"(v.y), "f"(v.z), "f"(v.w)
                 : "memory");
}

// ---------------- hs = relu(agg1*norm_dst + b0) * norm_src -------------------
__global__ void k_hs(const float* __restrict__ b0) {
    int tid = blockIdx.x * blockDim.x + threadIdx.x;
    if (tid >= NN * 16) return;
    int i = tid >> 4, c4 = (tid & 15) << 2;
    float nd = g_norm_dst[i], ns = g_norm_src[i];
    float4 a = *(const float4*)&g_agg1[i * HID + c4];
    float4 b = *(const float4*)&b0[c4];
    float4 o;
    o.x = fmaxf(fmaf(a.x, nd, b.x), 0.f) * ns;
    o.y = fmaxf(fmaf(a.y, nd, b.y), 0.f) * ns;
    o.z = fmaxf(fmaf(a.z, nd, b.z), 0.f) * ns;
    o.w = fmaxf(fmaf(a.w, nd, b.w), 0.f) * ns;
    *(float4*)&g_hs[i * HID + c4] = o;
}

// ---------------- fused GEMM2 + epilogue --------------------------------------
// z = agg2*norm_dst; out[i,g] = (z.W1[:,g]+b1[g])*xu[i,g] + (z.W1[:,g+1000]+b1[g+1000])*xs[i,g]
__global__ __launch_bounds__(256) void k_out(
    const float* __restrict__ xu, const float* __restrict__ xs,
    const float* __restrict__ W1, const float* __restrict__ b1,
    float* __restrict__ out) {
    extern __shared__ float sm[];
    float* zT = sm;               // [64][132] transposed, padded
    float* Wb = sm + 64 * 132;    // [64][64]
    float* Wg = Wb + 64 * 64;     // [64][64]

    int i0 = blockIdx.y * 128;
    int g0 = blockIdx.x * 64;
    int tid = threadIdx.x;

    // z tile (scaled by norm_dst), transposed — float4 loads
    #pragma unroll
    for (int it = 0; it < 8; it++) {
        int idx = it * 256 + tid;             // 0..2047 float4s (128 rows x 16)
        int r = idx >> 4, k4 = (idx & 15) << 2;
        int i = i0 + r;
        float4 v = make_float4(0.f, 0.f, 0.f, 0.f);
        float nd = 0.f;
        if (i < NN) {
            v = *(const float4*)&g_agg2[i * HID + k4];
            nd = g_norm_dst[i];
        }
        zT[(k4 + 0) * 132 + r] = v.x * nd;
        zT[(k4 + 1) * 132 + r] = v.y * nd;
        zT[(k4 + 2) * 132 + r] = v.z * nd;
        zT[(k4 + 3) * 132 + r] = v.w * nd;
    }
    // W tiles (beta + gamma halves) — float4 loads, 64 k-rows x 16 float4 each
    #pragma unroll
    for (int it = 0; it < 4; it++) {
        int idx = it * 256 + tid;             // 0..1023
        int k = idx >> 4, c4 = (idx & 15) << 2;
        int g = g0 + c4;
        float4 wb = make_float4(0.f, 0.f, 0.f, 0.f);
        float4 wg = make_float4(0.f, 0.f, 0.f, 0.f);
        if (g < NG) {
            wb = *(const float4*)&W1[k * 2 * NG + g];
            wg = *(const float4*)&W1[k * 2 * NG + NG + g];
        }
        *(float4*)&Wb[k * 64 + c4] = wb;
        *(float4*)&Wg[k * 64 + c4] = wg;
    }
    __syncthreads();

    int ty = tid >> 4, tx = tid & 15;
    int r0 = ty * 8, cg = tx * 4;

    u64 aB[4][4] = {}, aG[4][4] = {};
    #pragma unroll 16
    for (int k = 0; k < HID; k++) {
        ulonglong2 a01 = *(const ulonglong2*)&zT[k * 132 + r0];
        ulonglong2 a23 = *(const ulonglong2*)&zT[k * 132 + r0 + 4];
        float4 wb = *(const float4*)&Wb[k * 64 + cg];
        float4 wg = *(const float4*)&Wg[k * 64 + cg];
        u64 ap[4] = {a01.x, a01.y, a23.x, a23.y};
        u64 wbs[4] = {splat2(wb.x), splat2(wb.y), splat2(wb.z), splat2(wb.w)};
        u64 wgs[4] = {splat2(wg.x), splat2(wg.y), splat2(wg.z), splat2(wg.w)};
        #pragma unroll
        for (int rp = 0; rp < 4; rp++) {
            #pragma unroll
            for (int j = 0; j < 4; j++) {
                ffma2(aB[rp][j], ap[rp], wbs[j]);
                ffma2(aG[rp][j], ap[rp], wgs[j]);
            }
        }
    }

    int g = g0 + cg;
    if (g < NG) {
        float4 bb = *(const float4*)&b1[g];
        float4 bg = *(const float4*)&b1[NG + g];
        float bbv[4] = {bb.x, bb.y, bb.z, bb.w};
        float bgv[4] = {bg.x, bg.y, bg.z, bg.w};
        #pragma unroll
        for (int rp = 0; rp < 4; rp++) {
            float bl[4], bh[4], gl[4], gh[4];
            #pragma unroll
            for (int j = 0; j < 4; j++) {
                unpack2(aB[rp][j], bl[j], bh[j]);
                unpack2(aG[rp][j], gl[j], gh[j]);
            }
            int il = i0 + r0 + rp * 2;
            if (il < NN) {
                float4 u = *(const float4*)&xu[il * NG + g];
                float4 s = *(const float4*)&xs[il * NG + g];
                float4 o;
                o.x = (bl[0] + bbv[0]) * u.x + (gl[0] + bgv[0]) * s.x;
                o.y = (bl[1] + bbv[1]) * u.y + (gl[1] + bgv[1]) * s.y;
                o.z = (bl[2] + bbv[2]) * u.z + (gl[2] + bgv[2]) * s.z;
                o.w = (bl[3] + bbv[3]) * u.w + (gl[3] + bgv[3]) * s.w;
                *(float4*)&out[il * NG + g] = o;
            }
            if (il + 1 < NN) {
                float4 u = *(const float4*)&xu[(il + 1) * NG + g];
                float4 s = *(const float4*)&xs[(il + 1) * NG + g];
                float4 o;
                o.x = (bh[0] + bbv[0]) * u.x + (gh[0] + bgv[0]) * s.x;
                o.y = (bh[1] + bbv[1]) * u.y + (gh[1] + bgv[1]) * s.y;
                o.z = (bh[2] + bbv[2]) * u.z + (gh[2] + bgv[2]) * s.z;
                o.w = (bh[3] + bbv[3]) * u.w + (gh[3] + bgv[3]) * s.w;
                *(float4*)&out[(il + 1) * NG + g] = o;
            }
        }
    }
}

// ---------------- host launcher -----------------------------------------------
extern "C" void kernel_launch(void* const* d_in, const int* in_sizes, int n_in,
                              void* d_out, int out_size) {
    const float* xu = (const float*)d_in[0];
    const float* xs = (const float*)d_in[1];
    const float* W0 = (const float*)d_in[2];
    const float* b0 = (const float*)d_in[3];
    const float* W1 = (const float*)d_in[4];
    const float* b1 = (const float*)d_in[5];
    const int* src = (const int*)d_in[6];
    const int* dst = (const int*)d_in[7];
    int E = in_sizes[6];
    float* out = (float*)d_out;

    void *p_dego, *p_degi, *p_agg1, *p_agg2, *p_t, *p_hs;
    cudaGetSymbolAddress(&p_dego, g_deg_out);
    cudaGetSymbolAddress(&p_degi, g_deg_in);
    cudaGetSymbolAddress(&p_agg1, g_agg1);
    cudaGetSymbolAddress(&p_agg2, g_agg2);
    cudaGetSymbolAddress(&p_t, g_t);
    cudaGetSymbolAddress(&p_hs, g_hs);

    cudaMemsetAsync(p_dego, 0, NN * sizeof(float), 0);
    cudaMemsetAsync(p_degi, 0, NN * sizeof(float), 0);
    cudaMemsetAsync(p_agg1, 0, (size_t)NN * HID * sizeof(float), 0);
    cudaMemsetAsync(p_agg2, 0, (size_t)NN * HID * sizeof(float), 0);

    k_deg<<<(E / 4 + 255) / 256, 256>>>(src, dst, E);
    k_norms<<<(NN + 255) / 256, 256>>>();
    k_gemm1<<<(NN + 127) / 128, 256>>>(xu, xs, W0);
    k_scatter<<<(int)(((long long)E * 16 + 255) / 256), 256>>>(src, dst, E, (const float*)p_t, (float*)p_agg1);
    k_hs<<<(NN * 16 + 255) / 256, 256>>>(b0);
    k_scatter<<<(int)(((long long)E * 16 + 255) / 256), 256>>>(src, dst, E, (const float*)p_hs, (float*)p_agg2);

    cudaFuncSetAttribute(k_out, cudaFuncAttributeMaxDynamicSharedMemorySize,
                         (64 * 132 + 2 * 64 * 64) * sizeof(float));
    k_out<<<dim3(16, (NN + 127) / 128), 256, (64 * 132 + 2 * 64 * 64) * sizeof(float)>>>(
        xu, xs, W1, b1, out);
}

// round 4
// speedup vs baseline: 1.5451x; 1.1341x over previous
#include <cuda_runtime.h>
#include <cuda_bf16.h>

#define NN 50000
#define NG 1000
#define HID 64
#define KPAD 72

typedef unsigned long long u64;
typedef unsigned int u32;

// ---------------- scratch ----------------------------------------------------
__device__ float g_t[NN * HID];
__device__ float g_agg1[NN * HID];
__device__ float g_hs[NN * HID];
__device__ float g_agg2[NN * HID];
__device__ float g_deg_out[NN];
__device__ float g_deg_in[NN];
__device__ float g_norm_src[NN];
__device__ float g_norm_dst[NN];

// ---------------- helpers -----------------------------------------------------
__device__ __forceinline__ void mma_bf16(float* d, u32 a0, u32 a1, u32 a2, u32 a3,
                                         u32 b0, u32 b1) {
    asm volatile(
        "mma.sync.aligned.m16n8k16.row.col.f32.bf16.bf16.f32 "
        "{%0,%1,%2,%3}, {%4,%5,%6,%7}, {%8,%9}, {%0,%1,%2,%3};"
        : "+f"(d[0]), "+f"(d[1]), "+f"(d[2]), "+f"(d[3])
        : "r"(a0), "r"(a1), "r"(a2), "r"(a3), "r"(b0), "r"(b1));
}

// pack 2 floats -> bf16x2 hi + bf16x2 residual lo
__device__ __forceinline__ void cvt_hilo2(float a, float b, u32& hi, u32& lo) {
    __nv_bfloat162 h = __floats2bfloat162_rn(a, b);
    float ra = a - __bfloat162float(h.x);
    float rb = b - __bfloat162float(h.y);
    __nv_bfloat162 l = __floats2bfloat162_rn(ra, rb);
    hi = *(u32*)&h; lo = *(u32*)&l;
}
__device__ __forceinline__ u32 ldsm_u32(const __nv_bfloat16* p) {
    return *(const u32*)p;
}

// ---------------- degree + norms ---------------------------------------------
__global__ void k_deg(const int* __restrict__ src, const int* __restrict__ dst, int E) {
    int e4 = (blockIdx.x * blockDim.x + threadIdx.x) * 4;
    if (e4 + 3 < E) {
        int4 s = *(const int4*)&src[e4];
        int4 d = *(const int4*)&dst[e4];
        atomicAdd(&g_deg_out[s.x], 1.0f); atomicAdd(&g_deg_out[s.y], 1.0f);
        atomicAdd(&g_deg_out[s.z], 1.0f); atomicAdd(&g_deg_out[s.w], 1.0f);
        atomicAdd(&g_deg_in[d.x], 1.0f);  atomicAdd(&g_deg_in[d.y], 1.0f);
        atomicAdd(&g_deg_in[d.z], 1.0f);  atomicAdd(&g_deg_in[d.w], 1.0f);
    } else {
        for (int e = e4; e < E; e++) {
            atomicAdd(&g_deg_out[src[e]], 1.0f);
            atomicAdd(&g_deg_in[dst[e]], 1.0f);
        }
    }
}

__global__ void k_norms() {
    int i = blockIdx.x * blockDim.x + threadIdx.x;
    if (i < NN) {
        g_norm_src[i] = rsqrtf(fmaxf(g_deg_out[i], 1.0f));
        g_norm_dst[i] = rsqrtf(fmaxf(g_deg_in[i], 1.0f));
    }
}

// ---------------- GEMM1 (mma.sync bf16 3-term): t = (concat @ W0) * norm_src --
// 256 thr = 8 warps; tile M=128, N=64; K=2000 in 32 chunks of 64
// smem bf16: Ah[128*72] Al[128*72] Bh[64*72] Bl[64*72] = 55296 B
#define G1_SMEM (384 * KPAD * 2)
__global__ __launch_bounds__(256) void k_gemm1_mma(
    const float* __restrict__ xu, const float* __restrict__ xs,
    const float* __restrict__ W0) {
    extern __shared__ __nv_bfloat16 sb[];
    __nv_bfloat16* Ah = sb;
    __nv_bfloat16* Al = Ah + 128 * KPAD;
    __nv_bfloat16* Bh = Al + 128 * KPAD;
    __nv_bfloat16* Bl = Bh + 64 * KPAD;

    int tid = threadIdx.x;
    int warp = tid >> 5, lane = tid & 31;
    int grp = lane >> 2, tig = lane & 3;
    int i0 = blockIdx.x * 128;
    int m0 = warp * 16;

    float acc[8][4];
    #pragma unroll
    for (int n = 0; n < 8; n++)
        #pragma unroll
        for (int j = 0; j < 4; j++) acc[n][j] = 0.f;

    for (int c = 0; c < 32; c++) {
        int kb = c * 64;
        if (c > 0) __syncthreads();

        // A chunk: 128 rows x 64 k (fp32 -> bf16 hi/lo)
        #pragma unroll
        for (int it = 0; it < 8; it++) {
            int idx = it * 256 + tid;            // 2048 float4
            int r = idx >> 4, kq = (idx & 15) << 2;
            int i = i0 + r, k = kb + kq;
            float4 v = make_float4(0.f, 0.f, 0.f, 0.f);
            if (i < NN && k < 2 * NG)
                v = (k < NG) ? *(const float4*)&xu[(size_t)i * NG + k]
                             : *(const float4*)&xs[(size_t)i * NG + (k - NG)];
            u32 h0, l0, h1, l1;
            cvt_hilo2(v.x, v.y, h0, l0);
            cvt_hilo2(v.z, v.w, h1, l1);
            *(uint2*)&Ah[r * KPAD + kq] = make_uint2(h0, h1);
            *(uint2*)&Al[r * KPAD + kq] = make_uint2(l0, l1);
        }
        // B chunk: Bs[n][kk] = W0[(kb+kk)*64 + n]
        #pragma unroll
        for (int it = 0; it < 16; it++) {
            int idx = it * 256 + tid;            // 4096 elems
            int kk = idx >> 6, n = idx & 63;
            int k = kb + kk;
            float w = (k < 2 * NG) ? W0[k * HID + n] : 0.f;
            __nv_bfloat16 wh = __float2bfloat16(w);
            __nv_bfloat16 wl = __float2bfloat16(w - __bfloat162float(wh));
            Bh[n * KPAD + kk] = wh;
            Bl[n * KPAD + kk] = wl;
        }
        __syncthreads();

        #pragma unroll
        for (int ks = 0; ks < 4; ks++) {
            int k0 = ks * 16;
            const __nv_bfloat16* ar0 = &Ah[(m0 + grp) * KPAD + k0 + 2 * tig];
            const __nv_bfloat16* ar1 = &Ah[(m0 + grp + 8) * KPAD + k0 + 2 * tig];
            u32 ah0 = ldsm_u32(ar0), ah1 = ldsm_u32(ar1);
            u32 ah2 = ldsm_u32(ar0 + 8), ah3 = ldsm_u32(ar1 + 8);
            const __nv_bfloat16* al0p = &Al[(m0 + grp) * KPAD + k0 + 2 * tig];
            const __nv_bfloat16* al1p = &Al[(m0 + grp + 8) * KPAD + k0 + 2 * tig];
            u32 al0 = ldsm_u32(al0p), al1 = ldsm_u32(al1p);
            u32 al2 = ldsm_u32(al0p + 8), al3 = ldsm_u32(al1p + 8);
            #pragma unroll
            for (int n = 0; n < 8; n++) {
                int nb = n * 8 + grp;
                const __nv_bfloat16* bp = &Bh[nb * KPAD + k0 + 2 * tig];
                const __nv_bfloat16* lp = &Bl[nb * KPAD + k0 + 2 * tig];
                u32 bh0 = ldsm_u32(bp), bh1 = ldsm_u32(bp + 8);
                u32 bl0 = ldsm_u32(lp), bl1 = ldsm_u32(lp + 8);
                mma_bf16(acc[n], ah0, ah1, ah2, ah3, bh0, bh1);
                mma_bf16(acc[n], ah0, ah1, ah2, ah3, bl0, bl1);
                mma_bf16(acc[n], al0, al1, al2, al3, bh0, bh1);
            }
        }
    }

    // epilogue: scale by norm_src, write g_t
    int r0 = i0 + m0 + grp;
    int r1 = r0 + 8;
    float ns0 = (r0 < NN) ? g_norm_src[r0] : 0.f;
    float ns1 = (r1 < NN) ? g_norm_src[r1] : 0.f;
    #pragma unroll
    for (int n = 0; n < 8; n++) {
        int col = n * 8 + tig * 2;
        if (r0 < NN)
            *(float2*)&g_t[(size_t)r0 * HID + col] = make_float2(acc[n][0] * ns0, acc[n][1] * ns0);
        if (r1 < NN)
            *(float2*)&g_t[(size_t)r1 * HID + col] = make_float2(acc[n][2] * ns1, acc[n][3] * ns1);
    }
}

// ---------------- edge scatter: agg[dst] += t[src], vector RED ----------------
__global__ void k_scatter(const int* __restrict__ src, const int* __restrict__ dst,
                          int E, const float* __restrict__ t, float* __restrict__ agg) {
    long long tid = (long long)blockIdx.x * blockDim.x + threadIdx.x;
    if (tid >= (long long)E * 16) return;
    int e = (int)(tid >> 4);
    int c4 = ((int)tid & 15) << 2;
    int s = src[e], d = dst[e];
    float4 v = *(const float4*)&t[s * HID + c4];
    asm volatile("red.global.add.v4.f32 [%0], {%1, %2, %3, %4};"
                 :: "l"(&agg[d * HID + c4]),
                    "f"(v.x), "f"(v.y), "f"(v.z), "f"(v.w)
                 : "memory");
}

// ---------------- hs = relu(agg1*norm_dst + b0) * norm_src -------------------
__global__ void k_hs(const float* __restrict__ b0) {
    int tid = blockIdx.x * blockDim.x + threadIdx.x;
    if (tid >= NN * 16) return;
    int i = tid >> 4, c4 = (tid & 15) << 2;
    float nd = g_norm_dst[i], ns = g_norm_src[i];
    float4 a = *(const float4*)&g_agg1[i * HID + c4];
    float4 b = *(const float4*)&b0[c4];
    float4 o;
    o.x = fmaxf(fmaf(a.x, nd, b.x), 0.f) * ns;
    o.y = fmaxf(fmaf(a.y, nd, b.y), 0.f) * ns;
    o.z = fmaxf(fmaf(a.z, nd, b.z), 0.f) * ns;
    o.w = fmaxf(fmaf(a.w, nd, b.w), 0.f) * ns;
    *(float4*)&g_hs[i * HID + c4] = o;
}

// ---------------- fused GEMM2 + epilogue (mma.sync) ----------------------------
// i-tile 128, gene-tile 64, K=64. beta = z@W1[:,g], gamma = z@W1[:,NG+g]
// smem bf16: Ah[128*72] Al[128*72] Bbh/Bbl/Bgh/Bgl[64*72] = 73728 B
#define KO_SMEM (512 * KPAD * 2)
__global__ __launch_bounds__(256) void k_out_mma(
    const float* __restrict__ xu, const float* __restrict__ xs,
    const float* __restrict__ W1, const float* __restrict__ b1,
    float* __restrict__ out) {
    extern __shared__ __nv_bfloat16 sb[];
    __nv_bfloat16* Ah = sb;
    __nv_bfloat16* Al = Ah + 128 * KPAD;
    __nv_bfloat16* Bbh = Al + 128 * KPAD;
    __nv_bfloat16* Bbl = Bbh + 64 * KPAD;
    __nv_bfloat16* Bgh = Bbl + 64 * KPAD;
    __nv_bfloat16* Bgl = Bgh + 64 * KPAD;

    int tid = threadIdx.x;
    int warp = tid >> 5, lane = tid & 31;
    int grp = lane >> 2, tig = lane & 3;
    int i0 = blockIdx.y * 128;
    int g0 = blockIdx.x * 64;
    int m0 = warp * 16;

    // A tile: z = agg2 * norm_dst (128 x 64)
    #pragma unroll
    for (int it = 0; it < 8; it++) {
        int idx = it * 256 + tid;
        int r = idx >> 4, kq = (idx & 15) << 2;
        int i = i0 + r;
        float4 v = make_float4(0.f, 0.f, 0.f, 0.f);
        float nd = 0.f;
        if (i < NN) {
            v = *(const float4*)&g_agg2[(size_t)i * HID + kq];
            nd = g_norm_dst[i];
        }
        u32 h0, l0, h1, l1;
        cvt_hilo2(v.x * nd, v.y * nd, h0, l0);
        cvt_hilo2(v.z * nd, v.w * nd, h1, l1);
        *(uint2*)&Ah[r * KPAD + kq] = make_uint2(h0, h1);
        *(uint2*)&Al[r * KPAD + kq] = make_uint2(l0, l1);
    }
    // B tiles
    #pragma unroll
    for (int it = 0; it < 16; it++) {
        int idx = it * 256 + tid;
        int kk = idx >> 6, n = idx & 63;
        int gg = g0 + n;
        float wb = 0.f, wg = 0.f;
        if (gg < NG) {
            wb = W1[kk * 2 * NG + gg];
            wg = W1[kk * 2 * NG + NG + gg];
        }
        __nv_bfloat16 wbh = __float2bfloat16(wb);
        __nv_bfloat16 wbl = __float2bfloat16(wb - __bfloat162float(wbh));
        __nv_bfloat16 wgh = __float2bfloat16(wg);
        __nv_bfloat16 wgl = __float2bfloat16(wg - __bfloat162float(wgh));
        Bbh[n * KPAD + kk] = wbh;
        Bbl[n * KPAD + kk] = wbl;
        Bgh[n * KPAD + kk] = wgh;
        Bgl[n * KPAD + kk] = wgl;
    }
    __syncthreads();

    float aB[8][4], aG[8][4];
    #pragma unroll
    for (int n = 0; n < 8; n++)
        #pragma unroll
        for (int j = 0; j < 4; j++) { aB[n][j] = 0.f; aG[n][j] = 0.f; }

    #pragma unroll
    for (int ks = 0; ks < 4; ks++) {
        int k0 = ks * 16;
        const __nv_bfloat16* ar0 = &Ah[(m0 + grp) * KPAD + k0 + 2 * tig];
        const __nv_bfloat16* ar1 = &Ah[(m0 + grp + 8) * KPAD + k0 + 2 * tig];
        u32 ah0 = ldsm_u32(ar0), ah1 = ldsm_u32(ar1);
        u32 ah2 = ldsm_u32(ar0 + 8), ah3 = ldsm_u32(ar1 + 8);
        const __nv_bfloat16* al0p = &Al[(m0 + grp) * KPAD + k0 + 2 * tig];
        const __nv_bfloat16* al1p = &Al[(m0 + grp + 8) * KPAD + k0 + 2 * tig];
        u32 al0 = ldsm_u32(al0p), al1 = ldsm_u32(al1p);
        u32 al2 = ldsm_u32(al0p + 8), al3 = ldsm_u32(al1p + 8);
        #pragma unroll
        for (int n = 0; n < 8; n++) {
            int nb = n * 8 + grp;
            const __nv_bfloat16* bp = &Bbh[nb * KPAD + k0 + 2 * tig];
            const __nv_bfloat16* lp = &Bbl[nb * KPAD + k0 + 2 * tig];
            u32 b0 = ldsm_u32(bp), b1r = ldsm_u32(bp + 8);
            u32 l0 = ldsm_u32(lp), l1 = ldsm_u32(lp + 8);
            mma_bf16(aB[n], ah0, ah1, ah2, ah3, b0, b1r);
            mma_bf16(aB[n], ah0, ah1, ah2, ah3, l0, l1);
            mma_bf16(aB[n], al0, al1, al2, al3, b0, b1r);
            const __nv_bfloat16* gp = &Bgh[nb * KPAD + k0 + 2 * tig];
            const __nv_bfloat16* hp = &Bgl[nb * KPAD + k0 + 2 * tig];
            u32 g0r = ldsm_u32(gp), g1r = ldsm_u32(gp + 8);
            u32 h0r = ldsm_u32(hp), h1r = ldsm_u32(hp + 8);
            mma_bf16(aG[n], ah0, ah1, ah2, ah3, g0r, g1r);
            mma_bf16(aG[n], ah0, ah1, ah2, ah3, h0r, h1r);
            mma_bf16(aG[n], al0, al1, al2, al3, g0r, g1r);
        }
    }

    // fused epilogue
    int r0 = i0 + m0 + grp;
    int r1 = r0 + 8;
    #pragma unroll
    for (int n = 0; n < 8; n++) {
        int gene = g0 + n * 8 + tig * 2;
        if (gene >= NG) continue;
        float2 bb = *(const float2*)&b1[gene];
        float2 bg = *(const float2*)&b1[NG + gene];
        if (r0 < NN) {
            float2 u = *(const float2*)&xu[(size_t)r0 * NG + gene];
            float2 s = *(const float2*)&xs[(size_t)r0 * NG + gene];
            float2 o;
            o.x = (aB[n][0] + bb.x) * u.x + (aG[n][0] + bg.x) * s.x;
            o.y = (aB[n][1] + bb.y) * u.y + (aG[n][1] + bg.y) * s.y;
            *(float2*)&out[(size_t)r0 * NG + gene] = o;
        }
        if (r1 < NN) {
            float2 u = *(const float2*)&xu[(size_t)r1 * NG + gene];
            float2 s = *(const float2*)&xs[(size_t)r1 * NG + gene];
            float2 o;
            o.x = (aB[n][2] + bb.x) * u.x + (aG[n][2] + bg.x) * s.x;
            o.y = (aB[n][3] + bb.y) * u.y + (aG[n][3] + bg.y) * s.y;
            *(float2*)&out[(size_t)r1 * NG + gene] = o;
        }
    }
}

// ---------------- host launcher -----------------------------------------------
extern "C" void kernel_launch(void* const* d_in, const int* in_sizes, int n_in,
                              void* d_out, int out_size) {
    const float* xu = (const float*)d_in[0];
    const float* xs = (const float*)d_in[1];
    const float* W0 = (const float*)d_in[2];
    const float* b0 = (const float*)d_in[3];
    const float* W1 = (const float*)d_in[4];
    const float* b1 = (const float*)d_in[5];
    const int* src = (const int*)d_in[6];
    const int* dst = (const int*)d_in[7];
    int E = in_sizes[6];
    float* out = (float*)d_out;

    void *p_dego, *p_degi, *p_agg1, *p_agg2, *p_t, *p_hs;
    cudaGetSymbolAddress(&p_dego, g_deg_out);
    cudaGetSymbolAddress(&p_degi, g_deg_in);
    cudaGetSymbolAddress(&p_agg1, g_agg1);
    cudaGetSymbolAddress(&p_agg2, g_agg2);
    cudaGetSymbolAddress(&p_t, g_t);
    cudaGetSymbolAddress(&p_hs, g_hs);

    cudaMemsetAsync(p_dego, 0, NN * sizeof(float), 0);
    cudaMemsetAsync(p_degi, 0, NN * sizeof(float), 0);
    cudaMemsetAsync(p_agg1, 0, (size_t)NN * HID * sizeof(float), 0);
    cudaMemsetAsync(p_agg2, 0, (size_t)NN * HID * sizeof(float), 0);

    static int attr_done = 0;
    if (!attr_done) {
        cudaFuncSetAttribute(k_gemm1_mma, cudaFuncAttributeMaxDynamicSharedMemorySize, G1_SMEM);
        cudaFuncSetAttribute(k_out_mma, cudaFuncAttributeMaxDynamicSharedMemorySize, KO_SMEM);
        attr_done = 1;
    }

    k_deg<<<(E / 4 + 255) / 256, 256>>>(src, dst, E);
    k_norms<<<(NN + 255) / 256, 256>>>();
    k_gemm1_mma<<<(NN + 127) / 128, 256, G1_SMEM>>>(xu, xs, W0);
    k_scatter<<<(int)(((long long)E * 16 + 255) / 256), 256>>>(src, dst, E, (const float*)p_t, (float*)p_agg1);
    k_hs<<<(NN * 16 + 255) / 256, 256>>>(b0);
    k_scatter<<<(int)(((long long)E * 16 + 255) / 256), 256>>>(src, dst, E, (const float*)p_hs, (float*)p_agg2);
    k_out_mma<<<dim3(16, (NN + 127) / 128), 256, KO_SMEM>>>(xu, xs, W1, b1, out);
}

// round 5
// speedup vs baseline: 2.0046x; 1.2974x over previous
#include <cuda_runtime.h>
#include <cuda_bf16.h>

#define NN 50000
#define NG 1000
#define HID 64
#define NE_MAX 1600000
#define KW 2048
#define KPAD 72
#define APAD 72
#define NB 49

typedef unsigned long long u64;
typedef unsigned int u32;

// ---------------- scratch ----------------------------------------------------
__device__ float g_t[NN * HID];
__device__ float g_hs[NN * HID];
__device__ float g_z[NN * HID];
__device__ int g_deg_in[NN];
__device__ int g_deg_out[NN];
__device__ int g_off[NN + 1];
__device__ int g_offtmp[NN];
__device__ int g_ctr[NN];
__device__ int g_bsum[NB];
__device__ int g_bpre[NB];
__device__ int g_csr[NE_MAX];
__device__ float g_norm_src[NN];
__device__ float g_norm_dst[NN];
__device__ __nv_bfloat16 g_W0h[HID * KW];    // [n][k], zero-padded k>=2000
__device__ __nv_bfloat16 g_W0l[HID * KW];
__device__ __nv_bfloat16 g_Bbh[1024 * HID];  // [gene][k], zero-padded gene>=1000
__device__ __nv_bfloat16 g_Bbl[1024 * HID];
__device__ __nv_bfloat16 g_Bgh[1024 * HID];
__device__ __nv_bfloat16 g_Bgl[1024 * HID];

// ---------------- helpers -----------------------------------------------------
__device__ __forceinline__ u32 smem_u32(const void* p) {
    u32 a;
    asm("{ .reg .u64 t; cvta.to.shared.u64 t, %1; cvt.u32.u64 %0, t; }" : "=r"(a) : "l"(p));
    return a;
}
__device__ __forceinline__ void mma_bf16(float* d, u32 a0, u32 a1, u32 a2, u32 a3,
                                         u32 b0, u32 b1) {
    asm volatile(
        "mma.sync.aligned.m16n8k16.row.col.f32.bf16.bf16.f32 "
        "{%0,%1,%2,%3}, {%4,%5,%6,%7}, {%8,%9}, {%0,%1,%2,%3};"
        : "+f"(d[0]), "+f"(d[1]), "+f"(d[2]), "+f"(d[3])
        : "r"(a0), "r"(a1), "r"(a2), "r"(a3), "r"(b0), "r"(b1));
}
__device__ __forceinline__ void cvt_hilo2(float a, float b, u32& hi, u32& lo) {
    __nv_bfloat162 h = __floats2bfloat162_rn(a, b);
    float ra = a - __bfloat162float(h.x);
    float rb = b - __bfloat162float(h.y);
    __nv_bfloat162 l = __floats2bfloat162_rn(ra, rb);
    hi = *(u32*)&h; lo = *(u32*)&l;
}
__device__ __forceinline__ void cp16(u32 daddr, const void* gp, int zf) {
    asm volatile("cp.async.ca.shared.global [%0], [%1], 16, %2;"
                 :: "r"(daddr), "l"(gp), "r"(zf));
}
__device__ __forceinline__ void cp16f(u32 daddr, const void* gp) {
    asm volatile("cp.async.ca.shared.global [%0], [%1], 16;"
                 :: "r"(daddr), "l"(gp));
}

// ---------------- weight pre-conversion ---------------------------------------
__global__ void k_prep(const float* __restrict__ W0, const float* __restrict__ W1) {
    int idx = blockIdx.x * blockDim.x + threadIdx.x;
    if (idx < HID * KW) {
        int n = idx / KW, k = idx % KW;
        float w = (k < 2 * NG) ? W0[k * HID + n] : 0.f;
        __nv_bfloat16 h = __float2bfloat16(w);
        g_W0h[idx] = h;
        g_W0l[idx] = __float2bfloat16(w - __bfloat162float(h));
    }
    if (idx < 1024 * HID) {
        int g = idx / HID, k = idx % HID;
        float wb = (g < NG) ? W1[k * 2 * NG + g] : 0.f;
        float wg = (g < NG) ? W1[k * 2 * NG + NG + g] : 0.f;
        __nv_bfloat16 bh = __float2bfloat16(wb);
        __nv_bfloat16 gh = __float2bfloat16(wg);
        g_Bbh[idx] = bh;
        g_Bbl[idx] = __float2bfloat16(wb - __bfloat162float(bh));
        g_Bgh[idx] = gh;
        g_Bgl[idx] = __float2bfloat16(wg - __bfloat162float(gh));
    }
}

// ---------------- degree count -------------------------------------------------
__global__ void k_count(const int* __restrict__ src, const int* __restrict__ dst, int E) {
    int e4 = (blockIdx.x * blockDim.x + threadIdx.x) * 4;
    if (e4 + 3 < E) {
        int4 s = *(const int4*)&src[e4];
        int4 d = *(const int4*)&dst[e4];
        atomicAdd(&g_deg_out[s.x], 1); atomicAdd(&g_deg_out[s.y], 1);
        atomicAdd(&g_deg_out[s.z], 1); atomicAdd(&g_deg_out[s.w], 1);
        atomicAdd(&g_deg_in[d.x], 1);  atomicAdd(&g_deg_in[d.y], 1);
        atomicAdd(&g_deg_in[d.z], 1);  atomicAdd(&g_deg_in[d.w], 1);
    } else {
        for (int e = e4; e < E; e++) {
            atomicAdd(&g_deg_out[src[e]], 1);
            atomicAdd(&g_deg_in[dst[e]], 1);
        }
    }
}

// ---------------- scan (exclusive offsets over deg_in) -------------------------
__global__ __launch_bounds__(1024) void k_scan1() {
    __shared__ int s[1024];
    int t = threadIdx.x;
    int i = blockIdx.x * 1024 + t;
    int v = (i < NN) ? g_deg_in[i] : 0;
    s[t] = v;
    __syncthreads();
    #pragma unroll
    for (int d = 1; d < 1024; d <<= 1) {
        int x = (t >= d) ? s[t - d] : 0;
        __syncthreads();
        s[t] += x;
        __syncthreads();
    }
    if (i < NN) g_offtmp[i] = s[t];
    if (t == 1023) g_bsum[blockIdx.x] = s[1023];
}

__global__ void k_scan2() {
    if (threadIdx.x == 0) {
        int run = 0;
        for (int b = 0; b < NB; b++) {
            g_bpre[b] = run;
            run += g_bsum[b];
        }
    }
}

__global__ __launch_bounds__(1024) void k_scan3() {
    int i = blockIdx.x * 1024 + threadIdx.x;
    if (i >= NN) return;
    int v = g_deg_in[i];
    int excl = g_offtmp[i] - v + g_bpre[blockIdx.x];
    g_off[i] = excl;
    if (i == NN - 1) g_off[NN] = excl + v;
    g_norm_dst[i] = rsqrtf(fmaxf((float)v, 1.0f));
    g_norm_src[i] = rsqrtf(fmaxf((float)g_deg_out[i], 1.0f));
}

// ---------------- CSR fill -----------------------------------------------------
__global__ void k_fill(const int* __restrict__ src, const int* __restrict__ dst, int E) {
    int e4 = (blockIdx.x * blockDim.x + threadIdx.x) * 4;
    if (e4 + 3 < E) {
        int4 s = *(const int4*)&src[e4];
        int4 d = *(const int4*)&dst[e4];
        g_csr[g_off[d.x] + atomicAdd(&g_ctr[d.x], 1)] = s.x;
        g_csr[g_off[d.y] + atomicAdd(&g_ctr[d.y], 1)] = s.y;
        g_csr[g_off[d.z] + atomicAdd(&g_ctr[d.z], 1)] = s.z;
        g_csr[g_off[d.w] + atomicAdd(&g_ctr[d.w], 1)] = s.w;
    } else {
        for (int e = e4; e < E; e++) {
            int d = dst[e];
            g_csr[g_off[d] + atomicAdd(&g_ctr[d], 1)] = src[e];
        }
    }
}

// ---------------- GEMM1: t = (concat(xu,xs) @ W0) * norm_src -------------------
// 256 thr, M=128, N=64, K=2000 in 32 chunks of 64; cp.async double-buffered
#define G1_SMEM (2 * 128 * APAD * 4 + 2 * 2 * 64 * KPAD * 2)
__global__ __launch_bounds__(256) void k_gemm1(
    const float* __restrict__ xu, const float* __restrict__ xs) {
    extern __shared__ __align__(16) char sm[];
    float* Af = (float*)sm;                                   // [2][128][APAD]
    __nv_bfloat16* Bsm = (__nv_bfloat16*)(sm + 2 * 128 * APAD * 4); // [2][h|l][64][KPAD]
    u32 aBase = smem_u32(sm);
    u32 bBase = aBase + 2 * 128 * APAD * 4;

    int tid = threadIdx.x, warp = tid >> 5, lane = tid & 31;
    int grp = lane >> 2, tig = lane & 3;
    int i0 = blockIdx.x * 128, m0 = warp * 16;

    float acc[8][4];
    #pragma unroll
    for (int n = 0; n < 8; n++)
        #pragma unroll
        for (int j = 0; j < 4; j++) acc[n][j] = 0.f;

    // ---- async load of chunk c into buffer c&1 ----
    auto loadA = [&](int c) {
        int kb = c * 64;
        u32 da = aBase + (u32)(c & 1) * 128 * APAD * 4;
        #pragma unroll
        for (int q = 0; q < 8; q++) {
            int idx = q * 256 + tid;
            int r = idx >> 4, kq = (idx & 15) << 2;
            int i = i0 + r, k = kb + kq;
            const float* gp = xu;
            int zf = 0;
            if (i < NN && k < 2 * NG) {
                gp = (k < NG) ? xu + (size_t)i * NG + k
                              : xs + (size_t)i * NG + (k - NG);
                zf = 16;
            }
            cp16(da + (r * APAD + kq) * 4, gp, zf);
        }
        u32 db = bBase + (u32)(c & 1) * (2 * 64 * KPAD * 2);
        #pragma unroll
        for (int q = 0; q < 4; q++) {
            int idx = q * 256 + tid;          // 1024 granules
            int arr = idx >> 9;               // 0:h 1:l
            int rem = idx & 511;
            int n = rem >> 3, kq = (rem & 7) << 3;
            const __nv_bfloat16* gp = (arr ? g_W0l : g_W0h) + n * KW + kb + kq;
            cp16f(db + arr * (64 * KPAD * 2) + (n * KPAD + kq) * 2, gp);
        }
        asm volatile("cp.async.commit_group;" ::: "memory");
    };

    loadA(0);
    for (int c = 0; c < 32; c++) {
        if (c < 31) {
            loadA(c + 1);
            asm volatile("cp.async.wait_group 1;" ::: "memory");
        } else {
            asm volatile("cp.async.wait_group 0;" ::: "memory");
        }
        __syncthreads();

        const float* A = Af + (c & 1) * 128 * APAD;
        const __nv_bfloat16* Bh = Bsm + (c & 1) * 2 * 64 * KPAD;
        const __nv_bfloat16* Bl = Bh + 64 * KPAD;

        #pragma unroll
        for (int ks = 0; ks < 4; ks++) {
            int k0 = ks * 16;
            float2 f0 = *(const float2*)&A[(m0 + grp) * APAD + k0 + 2 * tig];
            float2 f1 = *(const float2*)&A[(m0 + grp + 8) * APAD + k0 + 2 * tig];
            float2 f2 = *(const float2*)&A[(m0 + grp) * APAD + k0 + 2 * tig + 8];
            float2 f3 = *(const float2*)&A[(m0 + grp + 8) * APAD + k0 + 2 * tig + 8];
            u32 ah0, al0, ah1, al1, ah2, al2, ah3, al3;
            cvt_hilo2(f0.x, f0.y, ah0, al0);
            cvt_hilo2(f1.x, f1.y, ah1, al1);
            cvt_hilo2(f2.x, f2.y, ah2, al2);
            cvt_hilo2(f3.x, f3.y, ah3, al3);
            #pragma unroll
            for (int n = 0; n < 8; n++) {
                int nb = n * 8 + grp;
                u32 bh0 = *(const u32*)&Bh[nb * KPAD + k0 + 2 * tig];
                u32 bh1 = *(const u32*)&Bh[nb * KPAD + k0 + 2 * tig + 8];
                u32 bl0 = *(const u32*)&Bl[nb * KPAD + k0 + 2 * tig];
                u32 bl1 = *(const u32*)&Bl[nb * KPAD + k0 + 2 * tig + 8];
                mma_bf16(acc[n], ah0, ah1, ah2, ah3, bh0, bh1);
                mma_bf16(acc[n], ah0, ah1, ah2, ah3, bl0, bl1);
                mma_bf16(acc[n], al0, al1, al2, al3, bh0, bh1);
            }
        }
        __syncthreads();
    }

    int r0 = i0 + m0 + grp;
    int r1 = r0 + 8;
    float ns0 = (r0 < NN) ? g_norm_src[r0] : 0.f;
    float ns1 = (r1 < NN) ? g_norm_src[r1] : 0.f;
    #pragma unroll
    for (int n = 0; n < 8; n++) {
        int col = n * 8 + tig * 2;
        if (r0 < NN)
            *(float2*)&g_t[(size_t)r0 * HID + col] = make_float2(acc[n][0] * ns0, acc[n][1] * ns0);
        if (r1 < NN)
            *(float2*)&g_t[(size_t)r1 * HID + col] = make_float2(acc[n][2] * ns1, acc[n][3] * ns1);
    }
}

// ---------------- CSR gather: warp per node ------------------------------------
// MODE 0: g_hs = relu(sum*nd + b0)*ns   MODE 1: g_z = sum*nd
template <int MODE>
__global__ __launch_bounds__(256) void k_gather(const float* __restrict__ t,
                                                const float* __restrict__ b0,
                                                float* __restrict__ o) {
    int gw = (blockIdx.x * 256 + threadIdx.x) >> 5;
    if (gw >= NN) return;
    int lane = threadIdx.x & 31;
    int beg = g_off[gw], end = g_off[gw + 1];

    float2 acc = make_float2(0.f, 0.f);
    int j = beg;
    for (; j + 4 <= end; j += 4) {
        int s0 = g_csr[j], s1 = g_csr[j + 1], s2 = g_csr[j + 2], s3 = g_csr[j + 3];
        float2 v0 = *(const float2*)&t[(size_t)s0 * HID + 2 * lane];
        float2 v1 = *(const float2*)&t[(size_t)s1 * HID + 2 * lane];
        float2 v2 = *(const float2*)&t[(size_t)s2 * HID + 2 * lane];
        float2 v3 = *(const float2*)&t[(size_t)s3 * HID + 2 * lane];
        acc.x += v0.x + v1.x + v2.x + v3.x;
        acc.y += v0.y + v1.y + v2.y + v3.y;
    }
    for (; j < end; j++) {
        int s = g_csr[j];
        float2 v = *(const float2*)&t[(size_t)s * HID + 2 * lane];
        acc.x += v.x; acc.y += v.y;
    }

    float nd = g_norm_dst[gw];
    float2 r;
    if (MODE == 0) {
        float ns = g_norm_src[gw];
        float2 b = *(const float2*)&b0[2 * lane];
        r.x = fmaxf(fmaf(acc.x, nd, b.x), 0.f) * ns;
        r.y = fmaxf(fmaf(acc.y, nd, b.y), 0.f) * ns;
    } else {
        r.x = acc.x * nd;
        r.y = acc.y * nd;
    }
    *(float2*)&o[(size_t)gw * HID + 2 * lane] = r;
}

// ---------------- fused GEMM2 + epilogue ----------------------------------------
// i-tile 128, gene-tile 64, K=64; A = g_z (already *nd), B = preconverted bf16
#define KO_SMEM (128 * APAD * 4 + 4 * 64 * KPAD * 2)
__global__ __launch_bounds__(256) void k_out(
    const float* __restrict__ xu, const float* __restrict__ xs,
    const float* __restrict__ b1, float* __restrict__ out) {
    extern __shared__ __align__(16) char sm[];
    float* Zf = (float*)sm;                                       // [128][APAD]
    __nv_bfloat16* Bsm = (__nv_bfloat16*)(sm + 128 * APAD * 4);   // [4][64][KPAD]
    u32 zBase = smem_u32(sm);
    u32 bBase = zBase + 128 * APAD * 4;

    int tid = threadIdx.x, warp = tid >> 5, lane = tid & 31;
    int grp = lane >> 2, tig = lane & 3;
    int i0 = blockIdx.y * 128;
    int g0 = blockIdx.x * 64;
    int m0 = warp * 16;

    // async loads
    #pragma unroll
    for (int q = 0; q < 8; q++) {
        int idx = q * 256 + tid;
        int r = idx >> 4, kq = (idx & 15) << 2;
        int i = i0 + r;
        const float* gp = g_z;
        int zf = 0;
        if (i < NN) { gp = g_z + (size_t)i * HID + kq; zf = 16; }
        cp16(zBase + (r * APAD + kq) * 4, gp, zf);
    }
    #pragma unroll
    for (int q = 0; q < 8; q++) {
        int idx = q * 256 + tid;          // 2048 granules
        int arr = idx >> 9;               // 0..3
        int rem = idx & 511;
        int n = rem >> 3, kq = (rem & 7) << 3;
        const __nv_bfloat16* base =
            (arr == 0) ? g_Bbh : (arr == 1) ? g_Bbl : (arr == 2) ? g_Bgh : g_Bgl;
        cp16f(bBase + arr * (64 * KPAD * 2) + (n * KPAD + kq) * 2,
              base + (g0 + n) * HID + kq);
    }
    asm volatile("cp.async.commit_group;" ::: "memory");
    asm volatile("cp.async.wait_group 0;" ::: "memory");
    __syncthreads();

    const __nv_bfloat16* Bbh = Bsm;
    const __nv_bfloat16* Bbl = Bsm + 64 * KPAD;
    const __nv_bfloat16* Bgh = Bsm + 2 * 64 * KPAD;
    const __nv_bfloat16* Bgl = Bsm + 3 * 64 * KPAD;

    float aB[8][4], aG[8][4];
    #pragma unroll
    for (int n = 0; n < 8; n++)
        #pragma unroll
        for (int j = 0; j < 4; j++) { aB[n][j] = 0.f; aG[n][j] = 0.f; }

    #pragma unroll
    for (int ks = 0; ks < 4; ks++) {
        int k0 = ks * 16;
        float2 f0 = *(const float2*)&Zf[(m0 + grp) * APAD + k0 + 2 * tig];
        float2 f1 = *(const float2*)&Zf[(m0 + grp + 8) * APAD + k0 + 2 * tig];
        float2 f2 = *(const float2*)&Zf[(m0 + grp) * APAD + k0 + 2 * tig + 8];
        float2 f3 = *(const float2*)&Zf[(m0 + grp + 8) * APAD + k0 + 2 * tig + 8];
        u32 ah0, al0, ah1, al1, ah2, al2, ah3, al3;
        cvt_hilo2(f0.x, f0.y, ah0, al0);
        cvt_hilo2(f1.x, f1.y, ah1, al1);
        cvt_hilo2(f2.x, f2.y, ah2, al2);
        cvt_hilo2(f3.x, f3.y, ah3, al3);
        #pragma unroll
        for (int n = 0; n < 8; n++) {
            int nb = n * 8 + grp;
            u32 b0r = *(const u32*)&Bbh[nb * KPAD + k0 + 2 * tig];
            u32 b1r = *(const u32*)&Bbh[nb * KPAD + k0 + 2 * tig + 8];
            u32 l0r = *(const u32*)&Bbl[nb * KPAD + k0 + 2 * tig];
            u32 l1r = *(const u32*)&Bbl[nb * KPAD + k0 + 2 * tig + 8];
            mma_bf16(aB[n], ah0, ah1, ah2, ah3, b0r, b1r);
            mma_bf16(aB[n], ah0, ah1, ah2, ah3, l0r, l1r);
            mma_bf16(aB[n], al0, al1, al2, al3, b0r, b1r);
            u32 g0r = *(const u32*)&Bgh[nb * KPAD + k0 + 2 * tig];
            u32 g1r = *(const u32*)&Bgh[nb * KPAD + k0 + 2 * tig + 8];
            u32 h0r = *(const u32*)&Bgl[nb * KPAD + k0 + 2 * tig];
            u32 h1r = *(const u32*)&Bgl[nb * KPAD + k0 + 2 * tig + 8];
            mma_bf16(aG[n], ah0, ah1, ah2, ah3, g0r, g1r);
            mma_bf16(aG[n], ah0, ah1, ah2, ah3, h0r, h1r);
            mma_bf16(aG[n], al0, al1, al2, al3, g0r, g1r);
        }
    }

    int r0 = i0 + m0 + grp;
    int r1 = r0 + 8;
    #pragma unroll
    for (int n = 0; n < 8; n++) {
        int gene = g0 + n * 8 + tig * 2;
        if (gene >= NG) continue;
        float2 bb = *(const float2*)&b1[gene];
        float2 bg = *(const float2*)&b1[NG + gene];
        if (r0 < NN) {
            float2 u = *(const float2*)&xu[(size_t)r0 * NG + gene];
            float2 s = *(const float2*)&xs[(size_t)r0 * NG + gene];
            float2 o;
            o.x = (aB[n][0] + bb.x) * u.x + (aG[n][0] + bg.x) * s.x;
            o.y = (aB[n][1] + bb.y) * u.y + (aG[n][1] + bg.y) * s.y;
            *(float2*)&out[(size_t)r0 * NG + gene] = o;
        }
        if (r1 < NN) {
            float2 u = *(const float2*)&xu[(size_t)r1 * NG + gene];
            float2 s = *(const float2*)&xs[(size_t)r1 * NG + gene];
            float2 o;
            o.x = (aB[n][2] + bb.x) * u.x + (aG[n][2] + bg.x) * s.x;
            o.y = (aB[n][3] + bb.y) * u.y + (aG[n][3] + bg.y) * s.y;
            *(float2*)&out[(size_t)r1 * NG + gene] = o;
        }
    }
}

// ---------------- host launcher -------------------------------------------------
extern "C" void kernel_launch(void* const* d_in, const int* in_sizes, int n_in,
                              void* d_out, int out_size) {
    const float* xu = (const float*)d_in[0];
    const float* xs = (const float*)d_in[1];
    const float* W0 = (const float*)d_in[2];
    const float* b0 = (const float*)d_in[3];
    const float* W1 = (const float*)d_in[4];
    const float* b1 = (const float*)d_in[5];
    const int* src = (const int*)d_in[6];
    const int* dst = (const int*)d_in[7];
    int E = in_sizes[6];
    float* out = (float*)d_out;

    void *p_degi, *p_dego, *p_ctr, *p_t, *p_hs;
    cudaGetSymbolAddress(&p_degi, g_deg_in);
    cudaGetSymbolAddress(&p_dego, g_deg_out);
    cudaGetSymbolAddress(&p_ctr, g_ctr);
    cudaGetSymbolAddress(&p_t, g_t);
    cudaGetSymbolAddress(&p_hs, g_hs);

    static int attr_done = 0;
    if (!attr_done) {
        cudaFuncSetAttribute(k_gemm1, cudaFuncAttributeMaxDynamicSharedMemorySize, G1_SMEM);
        cudaFuncSetAttribute(k_out, cudaFuncAttributeMaxDynamicSharedMemorySize, KO_SMEM);
        attr_done = 1;
    }

    cudaMemsetAsync(p_degi, 0, NN * sizeof(int), 0);
    cudaMemsetAsync(p_dego, 0, NN * sizeof(int), 0);
    cudaMemsetAsync(p_ctr, 0, NN * sizeof(int), 0);

    k_prep<<<(HID * KW + 255) / 256, 256>>>(W0, W1);
    k_count<<<(E / 4 + 255) / 256, 256>>>(src, dst, E);
    k_scan1<<<NB, 1024>>>();
    k_scan2<<<1, 32>>>();
    k_scan3<<<NB, 1024>>>();
    k_fill<<<(E / 4 + 255) / 256, 256>>>(src, dst, E);
    k_gemm1<<<(NN + 127) / 128, 256, G1_SMEM>>>(xu, xs);
    k_gather<0><<<(NN * 32 + 255) / 256, 256>>>((const float*)p_t, b0, (float*)p_hs);
    {
        void* p_z; cudaGetSymbolAddress(&p_z, g_z);
        k_gather<1><<<(NN * 32 + 255) / 256, 256>>>((const float*)p_hs, b0, (float*)p_z);
    }
    k_out<<<dim3(16, (NN + 127) / 128), 256, KO_SMEM>>>(xu, xs, b1, out);
}

// round 6
// speedup vs baseline: 2.0133x; 1.0043x over previous
#include <cuda_runtime.h>
#include <cuda_bf16.h>

#define NN 50000
#define NG 1000
#define HID 64
#define NE_MAX 1600000
#define KW 2048
#define KPAD 72
#define APAD 72
#define NB 49

typedef unsigned long long u64;
typedef unsigned int u32;

// ---------------- scratch ----------------------------------------------------
__device__ float g_t[NN * HID];
__device__ float g_hs[NN * HID];
__device__ float g_z[NN * HID];
__device__ int g_deg_in[NN];
__device__ int g_deg_out[NN];
__device__ int g_off[NN + 1];
__device__ int g_offtmp[NN];
__device__ int g_ctr[NN];
__device__ int g_bsum[NB];
__device__ int g_bpre[NB];
__device__ int g_csr[NE_MAX];
__device__ float g_norm_src[NN];
__device__ float g_norm_dst[NN];
__device__ __nv_bfloat16 g_W0h[HID * KW];
__device__ __nv_bfloat16 g_W0l[HID * KW];
__device__ __nv_bfloat16 g_Bbh[1024 * HID];
__device__ __nv_bfloat16 g_Bbl[1024 * HID];
__device__ __nv_bfloat16 g_Bgh[1024 * HID];
__device__ __nv_bfloat16 g_Bgl[1024 * HID];

// ---------------- helpers -----------------------------------------------------
__device__ __forceinline__ u32 smem_u32(const void* p) {
    u32 a;
    asm("{ .reg .u64 t; cvta.to.shared.u64 t, %1; cvt.u32.u64 %0, t; }" : "=r"(a) : "l"(p));
    return a;
}
__device__ __forceinline__ void mma_bf16(float* d, u32 a0, u32 a1, u32 a2, u32 a3,
                                         u32 b0, u32 b1) {
    asm volatile(
        "mma.sync.aligned.m16n8k16.row.col.f32.bf16.bf16.f32 "
        "{%0,%1,%2,%3}, {%4,%5,%6,%7}, {%8,%9}, {%0,%1,%2,%3};"
        : "+f"(d[0]), "+f"(d[1]), "+f"(d[2]), "+f"(d[3])
        : "r"(a0), "r"(a1), "r"(a2), "r"(a3), "r"(b0), "r"(b1));
}
__device__ __forceinline__ void cvt_hilo2(float a, float b, u32& hi, u32& lo) {
    __nv_bfloat162 h = __floats2bfloat162_rn(a, b);
    float ra = a - __bfloat162float(h.x);
    float rb = b - __bfloat162float(h.y);
    __nv_bfloat162 l = __floats2bfloat162_rn(ra, rb);
    hi = *(u32*)&h; lo = *(u32*)&l;
}
__device__ __forceinline__ void cp16(u32 daddr, const void* gp, int zf) {
    asm volatile("cp.async.ca.shared.global [%0], [%1], 16, %2;"
                 :: "r"(daddr), "l"(gp), "r"(zf));
}
__device__ __forceinline__ void cp16f(u32 daddr, const void* gp) {
    asm volatile("cp.async.ca.shared.global [%0], [%1], 16;"
                 :: "r"(daddr), "l"(gp));
}

// ---------------- weight pre-conversion ---------------------------------------
__global__ void k_prep(const float* __restrict__ W0, const float* __restrict__ W1) {
    int idx = blockIdx.x * blockDim.x + threadIdx.x;
    if (idx < HID * KW) {
        int n = idx / KW, k = idx % KW;
        float w = (k < 2 * NG) ? W0[k * HID + n] : 0.f;
        __nv_bfloat16 h = __float2bfloat16(w);
        g_W0h[idx] = h;
        g_W0l[idx] = __float2bfloat16(w - __bfloat162float(h));
    }
    if (idx < 1024 * HID) {
        int g = idx / HID, k = idx % HID;
        float wb = (g < NG) ? W1[k * 2 * NG + g] : 0.f;
        float wg = (g < NG) ? W1[k * 2 * NG + NG + g] : 0.f;
        __nv_bfloat16 bh = __float2bfloat16(wb);
        __nv_bfloat16 gh = __float2bfloat16(wg);
        g_Bbh[idx] = bh;
        g_Bbl[idx] = __float2bfloat16(wb - __bfloat162float(bh));
        g_Bgh[idx] = gh;
        g_Bgl[idx] = __float2bfloat16(wg - __bfloat162float(gh));
    }
}

// ---------------- degree count -------------------------------------------------
__global__ void k_count(const int* __restrict__ src, const int* __restrict__ dst, int E) {
    int e4 = (blockIdx.x * blockDim.x + threadIdx.x) * 4;
    if (e4 + 3 < E) {
        int4 s = *(const int4*)&src[e4];
        int4 d = *(const int4*)&dst[e4];
        atomicAdd(&g_deg_out[s.x], 1); atomicAdd(&g_deg_out[s.y], 1);
        atomicAdd(&g_deg_out[s.z], 1); atomicAdd(&g_deg_out[s.w], 1);
        atomicAdd(&g_deg_in[d.x], 1);  atomicAdd(&g_deg_in[d.y], 1);
        atomicAdd(&g_deg_in[d.z], 1);  atomicAdd(&g_deg_in[d.w], 1);
    } else {
        for (int e = e4; e < E; e++) {
            atomicAdd(&g_deg_out[src[e]], 1);
            atomicAdd(&g_deg_in[dst[e]], 1);
        }
    }
}

// ---------------- scan ----------------------------------------------------------
__global__ __launch_bounds__(1024) void k_scan1() {
    __shared__ int s[1024];
    int t = threadIdx.x;
    int i = blockIdx.x * 1024 + t;
    int v = (i < NN) ? g_deg_in[i] : 0;
    s[t] = v;
    __syncthreads();
    #pragma unroll
    for (int d = 1; d < 1024; d <<= 1) {
        int x = (t >= d) ? s[t - d] : 0;
        __syncthreads();
        s[t] += x;
        __syncthreads();
    }
    if (i < NN) g_offtmp[i] = s[t];
    if (t == 1023) g_bsum[blockIdx.x] = s[1023];
}

__global__ void k_scan2() {
    __shared__ int s[64];
    int t = threadIdx.x;              // 64 threads
    int v = (t < NB) ? g_bsum[t] : 0;
    s[t] = v;
    __syncthreads();
    #pragma unroll
    for (int d = 1; d < 64; d <<= 1) {
        int x = (t >= d) ? s[t - d] : 0;
        __syncthreads();
        s[t] += x;
        __syncthreads();
    }
    if (t < NB) g_bpre[t] = s[t] - v;   // exclusive
}

__global__ __launch_bounds__(1024) void k_scan3() {
    int i = blockIdx.x * 1024 + threadIdx.x;
    if (i >= NN) return;
    int v = g_deg_in[i];
    int excl = g_offtmp[i] - v + g_bpre[blockIdx.x];
    g_off[i] = excl;
    if (i == NN - 1) g_off[NN] = excl + v;
    g_norm_dst[i] = rsqrtf(fmaxf((float)v, 1.0f));
    g_norm_src[i] = rsqrtf(fmaxf((float)g_deg_out[i], 1.0f));
}

// ---------------- CSR fill -------------------------------------------------------
__global__ void k_fill(const int* __restrict__ src, const int* __restrict__ dst, int E) {
    int e4 = (blockIdx.x * blockDim.x + threadIdx.x) * 4;
    if (e4 + 3 < E) {
        int4 s = *(const int4*)&src[e4];
        int4 d = *(const int4*)&dst[e4];
        g_csr[g_off[d.x] + atomicAdd(&g_ctr[d.x], 1)] = s.x;
        g_csr[g_off[d.y] + atomicAdd(&g_ctr[d.y], 1)] = s.y;
        g_csr[g_off[d.z] + atomicAdd(&g_ctr[d.z], 1)] = s.z;
        g_csr[g_off[d.w] + atomicAdd(&g_ctr[d.w], 1)] = s.w;
    } else {
        for (int e = e4; e < E; e++) {
            int d = dst[e];
            g_csr[g_off[d] + atomicAdd(&g_ctr[d], 1)] = src[e];
        }
    }
}

// ---------------- GEMM1: g_t = concat(xu,xs) @ W0 (UNscaled) --------------------
#define G1_SMEM (2 * 128 * APAD * 4 + 2 * 2 * 64 * KPAD * 2)
__global__ __launch_bounds__(256) void k_gemm1(
    const float* __restrict__ xu, const float* __restrict__ xs) {
    extern __shared__ __align__(16) char sm[];
    float* Af = (float*)sm;
    __nv_bfloat16* Bsm = (__nv_bfloat16*)(sm + 2 * 128 * APAD * 4);
    u32 aBase = smem_u32(sm);
    u32 bBase = aBase + 2 * 128 * APAD * 4;

    int tid = threadIdx.x, warp = tid >> 5, lane = tid & 31;
    int grp = lane >> 2, tig = lane & 3;
    int i0 = blockIdx.x * 128, m0 = warp * 16;

    float acc[8][4];
    #pragma unroll
    for (int n = 0; n < 8; n++)
        #pragma unroll
        for (int j = 0; j < 4; j++) acc[n][j] = 0.f;

    auto loadA = [&](int c) {
        int kb = c * 64;
        u32 da = aBase + (u32)(c & 1) * 128 * APAD * 4;
        #pragma unroll
        for (int q = 0; q < 8; q++) {
            int idx = q * 256 + tid;
            int r = idx >> 4, kq = (idx & 15) << 2;
            int i = i0 + r, k = kb + kq;
            const float* gp = xu;
            int zf = 0;
            if (i < NN && k < 2 * NG) {
                gp = (k < NG) ? xu + (size_t)i * NG + k
                              : xs + (size_t)i * NG + (k - NG);
                zf = 16;
            }
            cp16(da + (r * APAD + kq) * 4, gp, zf);
        }
        u32 db = bBase + (u32)(c & 1) * (2 * 64 * KPAD * 2);
        #pragma unroll
        for (int q = 0; q < 4; q++) {
            int idx = q * 256 + tid;
            int arr = idx >> 9;
            int rem = idx & 511;
            int n = rem >> 3, kq = (rem & 7) << 3;
            const __nv_bfloat16* gp = (arr ? g_W0l : g_W0h) + n * KW + kb + kq;
            cp16f(db + arr * (64 * KPAD * 2) + (n * KPAD + kq) * 2, gp);
        }
        asm volatile("cp.async.commit_group;" ::: "memory");
    };

    loadA(0);
    for (int c = 0; c < 32; c++) {
        if (c < 31) {
            loadA(c + 1);
            asm volatile("cp.async.wait_group 1;" ::: "memory");
        } else {
            asm volatile("cp.async.wait_group 0;" ::: "memory");
        }
        __syncthreads();

        const float* A = Af + (c & 1) * 128 * APAD;
        const __nv_bfloat16* Bh = Bsm + (c & 1) * 2 * 64 * KPAD;
        const __nv_bfloat16* Bl = Bh + 64 * KPAD;

        #pragma unroll
        for (int ks = 0; ks < 4; ks++) {
            int k0 = ks * 16;
            float2 f0 = *(const float2*)&A[(m0 + grp) * APAD + k0 + 2 * tig];
            float2 f1 = *(const float2*)&A[(m0 + grp + 8) * APAD + k0 + 2 * tig];
            float2 f2 = *(const float2*)&A[(m0 + grp) * APAD + k0 + 2 * tig + 8];
            float2 f3 = *(const float2*)&A[(m0 + grp + 8) * APAD + k0 + 2 * tig + 8];
            u32 ah0, al0, ah1, al1, ah2, al2, ah3, al3;
            cvt_hilo2(f0.x, f0.y, ah0, al0);
            cvt_hilo2(f1.x, f1.y, ah1, al1);
            cvt_hilo2(f2.x, f2.y, ah2, al2);
            cvt_hilo2(f3.x, f3.y, ah3, al3);
            #pragma unroll
            for (int n = 0; n < 8; n++) {
                int nb = n * 8 + grp;
                u32 bh0 = *(const u32*)&Bh[nb * KPAD + k0 + 2 * tig];
                u32 bh1 = *(const u32*)&Bh[nb * KPAD + k0 + 2 * tig + 8];
                u32 bl0 = *(const u32*)&Bl[nb * KPAD + k0 + 2 * tig];
                u32 bl1 = *(const u32*)&Bl[nb * KPAD + k0 + 2 * tig + 8];
                mma_bf16(acc[n], ah0, ah1, ah2, ah3, bh0, bh1);
                mma_bf16(acc[n], ah0, ah1, ah2, ah3, bl0, bl1);
                mma_bf16(acc[n], al0, al1, al2, al3, bh0, bh1);
            }
        }
        __syncthreads();
    }

    int r0 = i0 + m0 + grp;
    int r1 = r0 + 8;
    #pragma unroll
    for (int n = 0; n < 8; n++) {
        int col = n * 8 + tig * 2;
        if (r0 < NN)
            *(float2*)&g_t[(size_t)r0 * HID + col] = make_float2(acc[n][0], acc[n][1]);
        if (r1 < NN)
            *(float2*)&g_t[(size_t)r1 * HID + col] = make_float2(acc[n][2], acc[n][3]);
    }
}

// ---------------- CSR gather: warp per node --------------------------------------
// MODE 0: per-edge scale by norm_src[s]; out = relu(sum*nd + b0)*ns
// MODE 1: plain sum (input rows pre-scaled);  out = sum*nd
template <int MODE>
__global__ __launch_bounds__(256) void k_gather(const float* __restrict__ t,
                                                const float* __restrict__ b0,
                                                float* __restrict__ o) {
    int gw = (blockIdx.x * 256 + threadIdx.x) >> 5;
    if (gw >= NN) return;
    int lane = threadIdx.x & 31;
    int beg = g_off[gw], end = g_off[gw + 1];

    float2 acc = make_float2(0.f, 0.f);
    int j = beg;
    for (; j + 4 <= end; j += 4) {
        int s0 = g_csr[j], s1 = g_csr[j + 1], s2 = g_csr[j + 2], s3 = g_csr[j + 3];
        float2 v0 = *(const float2*)&t[(size_t)s0 * HID + 2 * lane];
        float2 v1 = *(const float2*)&t[(size_t)s1 * HID + 2 * lane];
        float2 v2 = *(const float2*)&t[(size_t)s2 * HID + 2 * lane];
        float2 v3 = *(const float2*)&t[(size_t)s3 * HID + 2 * lane];
        if (MODE == 0) {
            float n0 = g_norm_src[s0], n1 = g_norm_src[s1];
            float n2 = g_norm_src[s2], n3 = g_norm_src[s3];
            acc.x = fmaf(v0.x, n0, fmaf(v1.x, n1, fmaf(v2.x, n2, fmaf(v3.x, n3, acc.x))));
            acc.y = fmaf(v0.y, n0, fmaf(v1.y, n1, fmaf(v2.y, n2, fmaf(v3.y, n3, acc.y))));
        } else {
            acc.x += v0.x + v1.x + v2.x + v3.x;
            acc.y += v0.y + v1.y + v2.y + v3.y;
        }
    }
    for (; j < end; j++) {
        int s = g_csr[j];
        float2 v = *(const float2*)&t[(size_t)s * HID + 2 * lane];
        if (MODE == 0) {
            float ns = g_norm_src[s];
            acc.x = fmaf(v.x, ns, acc.x);
            acc.y = fmaf(v.y, ns, acc.y);
        } else {
            acc.x += v.x; acc.y += v.y;
        }
    }

    float nd = g_norm_dst[gw];
    float2 r;
    if (MODE == 0) {
        float ns = g_norm_src[gw];
        float2 b = *(const float2*)&b0[2 * lane];
        r.x = fmaxf(fmaf(acc.x, nd, b.x), 0.f) * ns;
        r.y = fmaxf(fmaf(acc.y, nd, b.y), 0.f) * ns;
    } else {
        r.x = acc.x * nd;
        r.y = acc.y * nd;
    }
    *(float2*)&o[(size_t)gw * HID + 2 * lane] = r;
}

// ---------------- fused GEMM2 + epilogue ------------------------------------------
#define KO_SMEM (128 * APAD * 4 + 4 * 64 * KPAD * 2)
__global__ __launch_bounds__(256) void k_out(
    const float* __restrict__ xu, const float* __restrict__ xs,
    const float* __restrict__ b1, float* __restrict__ out) {
    extern __shared__ __align__(16) char sm[];
    float* Zf = (float*)sm;
    __nv_bfloat16* Bsm = (__nv_bfloat16*)(sm + 128 * APAD * 4);
    u32 zBase = smem_u32(sm);
    u32 bBase = zBase + 128 * APAD * 4;

    int tid = threadIdx.x, warp = tid >> 5, lane = tid & 31;
    int grp = lane >> 2, tig = lane & 3;
    int i0 = blockIdx.y * 128;
    int g0 = blockIdx.x * 64;
    int m0 = warp * 16;

    #pragma unroll
    for (int q = 0; q < 8; q++) {
        int idx = q * 256 + tid;
        int r = idx >> 4, kq = (idx & 15) << 2;
        int i = i0 + r;
        const float* gp = g_z;
        int zf = 0;
        if (i < NN) { gp = g_z + (size_t)i * HID + kq; zf = 16; }
        cp16(zBase + (r * APAD + kq) * 4, gp, zf);
    }
    #pragma unroll
    for (int q = 0; q < 8; q++) {
        int idx = q * 256 + tid;
        int arr = idx >> 9;
        int rem = idx & 511;
        int n = rem >> 3, kq = (rem & 7) << 3;
        const __nv_bfloat16* base =
            (arr == 0) ? g_Bbh : (arr == 1) ? g_Bbl : (arr == 2) ? g_Bgh : g_Bgl;
        cp16f(bBase + arr * (64 * KPAD * 2) + (n * KPAD + kq) * 2,
              base + (g0 + n) * HID + kq);
    }
    asm volatile("cp.async.commit_group;" ::: "memory");
    asm volatile("cp.async.wait_group 0;" ::: "memory");
    __syncthreads();

    const __nv_bfloat16* Bbh = Bsm;
    const __nv_bfloat16* Bbl = Bsm + 64 * KPAD;
    const __nv_bfloat16* Bgh = Bsm + 2 * 64 * KPAD;
    const __nv_bfloat16* Bgl = Bsm + 3 * 64 * KPAD;

    float aB[8][4], aG[8][4];
    #pragma unroll
    for (int n = 0; n < 8; n++)
        #pragma unroll
        for (int j = 0; j < 4; j++) { aB[n][j] = 0.f; aG[n][j] = 0.f; }

    #pragma unroll
    for (int ks = 0; ks < 4; ks++) {
        int k0 = ks * 16;
        float2 f0 = *(const float2*)&Zf[(m0 + grp) * APAD + k0 + 2 * tig];
        float2 f1 = *(const float2*)&Zf[(m0 + grp + 8) * APAD + k0 + 2 * tig];
        float2 f2 = *(const float2*)&Zf[(m0 + grp) * APAD + k0 + 2 * tig + 8];
        float2 f3 = *(const float2*)&Zf[(m0 + grp + 8) * APAD + k0 + 2 * tig + 8];
        u32 ah0, al0, ah1, al1, ah2, al2, ah3, al3;
        cvt_hilo2(f0.x, f0.y, ah0, al0);
        cvt_hilo2(f1.x, f1.y, ah1, al1);
        cvt_hilo2(f2.x, f2.y, ah2, al2);
        cvt_hilo2(f3.x, f3.y, ah3, al3);
        #pragma unroll
        for (int n = 0; n < 8; n++) {
            int nb = n * 8 + grp;
            u32 b0r = *(const u32*)&Bbh[nb * KPAD + k0 + 2 * tig];
            u32 b1r = *(const u32*)&Bbh[nb * KPAD + k0 + 2 * tig + 8];
            u32 l0r = *(const u32*)&Bbl[nb * KPAD + k0 + 2 * tig];
            u32 l1r = *(const u32*)&Bbl[nb * KPAD + k0 + 2 * tig + 8];
            mma_bf16(aB[n], ah0, ah1, ah2, ah3, b0r, b1r);
            mma_bf16(aB[n], ah0, ah1, ah2, ah3, l0r, l1r);
            mma_bf16(aB[n], al0, al1, al2, al3, b0r, b1r);
            u32 g0r = *(const u32*)&Bgh[nb * KPAD + k0 + 2 * tig];
            u32 g1r = *(const u32*)&Bgh[nb * KPAD + k0 + 2 * tig + 8];
            u32 h0r = *(const u32*)&Bgl[nb * KPAD + k0 + 2 * tig];
            u32 h1r = *(const u32*)&Bgl[nb * KPAD + k0 + 2 * tig + 8];
            mma_bf16(aG[n], ah0, ah1, ah2, ah3, g0r, g1r);
            mma_bf16(aG[n], ah0, ah1, ah2, ah3, h0r, h1r);
            mma_bf16(aG[n], al0, al1, al2, al3, g0r, g1r);
        }
    }

    int r0 = i0 + m0 + grp;
    int r1 = r0 + 8;
    #pragma unroll
    for (int n = 0; n < 8; n++) {
        int gene = g0 + n * 8 + tig * 2;
        if (gene >= NG) continue;
        float2 bb = *(const float2*)&b1[gene];
        float2 bg = *(const float2*)&b1[NG + gene];
        if (r0 < NN) {
            float2 u = *(const float2*)&xu[(size_t)r0 * NG + gene];
            float2 s = *(const float2*)&xs[(size_t)r0 * NG + gene];
            float2 o;
            o.x = (aB[n][0] + bb.x) * u.x + (aG[n][0] + bg.x) * s.x;
            o.y = (aB[n][1] + bb.y) * u.y + (aG[n][1] + bg.y) * s.y;
            *(float2*)&out[(size_t)r0 * NG + gene] = o;
        }
        if (r1 < NN) {
            float2 u = *(const float2*)&xu[(size_t)r1 * NG + gene];
            float2 s = *(const float2*)&xs[(size_t)r1 * NG + gene];
            float2 o;
            o.x = (aB[n][2] + bb.x) * u.x + (aG[n][2] + bg.x) * s.x;
            o.y = (aB[n][3] + bb.y) * u.y + (aG[n][3] + bg.y) * s.y;
            *(float2*)&out[(size_t)r1 * NG + gene] = o;
        }
    }
}

// ---------------- host launcher ---------------------------------------------------
extern "C" void kernel_launch(void* const* d_in, const int* in_sizes, int n_in,
                              void* d_out, int out_size) {
    const float* xu = (const float*)d_in[0];
    const float* xs = (const float*)d_in[1];
    const float* W0 = (const float*)d_in[2];
    const float* b0 = (const float*)d_in[3];
    const float* W1 = (const float*)d_in[4];
    const float* b1 = (const float*)d_in[5];
    const int* src = (const int*)d_in[6];
    const int* dst = (const int*)d_in[7];
    int E = in_sizes[6];
    float* out = (float*)d_out;

    void *p_degi, *p_dego, *p_ctr, *p_t, *p_hs, *p_z;
    cudaGetSymbolAddress(&p_degi, g_deg_in);
    cudaGetSymbolAddress(&p_dego, g_deg_out);
    cudaGetSymbolAddress(&p_ctr, g_ctr);
    cudaGetSymbolAddress(&p_t, g_t);
    cudaGetSymbolAddress(&p_hs, g_hs);
    cudaGetSymbolAddress(&p_z, g_z);

    static cudaStream_t s1 = nullptr;
    static cudaEvent_t evFork = nullptr, evJoin = nullptr;
    static int attr_done = 0;
    if (!attr_done) {
        cudaFuncSetAttribute(k_gemm1, cudaFuncAttributeMaxDynamicSharedMemorySize, G1_SMEM);
        cudaFuncSetAttribute(k_out, cudaFuncAttributeMaxDynamicSharedMemorySize, KO_SMEM);
        cudaStreamCreateWithFlags(&s1, cudaStreamNonBlocking);
        cudaEventCreateWithFlags(&evFork, cudaEventDisableTiming);
        cudaEventCreateWithFlags(&evJoin, cudaEventDisableTiming);
        attr_done = 1;
    }

    // fork: chain B (CSR build) on s1, chain A (weights + gemm1) on main stream
    cudaEventRecord(evFork, 0);
    cudaStreamWaitEvent(s1, evFork, 0);

    // chain B
    cudaMemsetAsync(p_degi, 0, NN * sizeof(int), s1);
    cudaMemsetAsync(p_dego, 0, NN * sizeof(int), s1);
    cudaMemsetAsync(p_ctr, 0, NN * sizeof(int), s1);
    k_count<<<(E / 4 + 255) / 256, 256, 0, s1>>>(src, dst, E);
    k_scan1<<<NB, 1024, 0, s1>>>();
    k_scan2<<<1, 64, 0, s1>>>();
    k_scan3<<<NB, 1024, 0, s1>>>();
    k_fill<<<(E / 4 + 255) / 256, 256, 0, s1>>>(src, dst, E);
    cudaEventRecord(evJoin, s1);

    // chain A
    k_prep<<<(HID * KW + 255) / 256, 256>>>(W0, W1);
    k_gemm1<<<(NN + 127) / 128, 256, G1_SMEM>>>(xu, xs);

    // join
    cudaStreamWaitEvent(0, evJoin, 0);

    k_gather<0><<<(NN * 32 + 255) / 256, 256>>>((const float*)p_t, b0, (float*)p_hs);
    k_gather<1><<<(NN * 32 + 255) / 256, 256>>>((const float*)p_hs, b0, (float*)p_z);
    k_out<<<dim3(16, (NN + 127) / 128), 256, KO_SMEM>>>(xu, xs, b1, out);
}

// round 7
// speedup vs baseline: 2.7545x; 1.3682x over previous
#include <cuda_runtime.h>
#include <cuda_bf16.h>
#include <cuda_fp16.h>

#define NN 50000
#define NG 1000
#define HID 64
#define NE_MAX 1600000
#define KW 2048
#define KPAD 72
#define APAD 72
#define NB 49

typedef unsigned long long u64;
typedef unsigned int u32;

// ---------------- scratch ----------------------------------------------------
__device__ float g_t[NN * HID];
__device__ float g_hs[NN * HID];
__device__ float g_z[NN * HID];
__device__ int g_deg_in[NN];
__device__ int g_deg_out[NN];
__device__ int g_off[NN + 1];
__device__ int g_offtmp[NN];
__device__ int g_ctr[NN];
__device__ int g_bsum[NB];
__device__ int g_bpre[NB];
__device__ int g_csr[NE_MAX];
__device__ float g_norm_src[NN];
__device__ float g_norm_dst[NN];
__device__ __half g_W0h[HID * KW];     // [n][k] fp16, zero-padded k>=2000
__device__ __half g_Bb[1024 * HID];    // [gene][k] fp16 beta cols
__device__ __half g_Bg[1024 * HID];    // [gene][k] fp16 gamma cols

// ---------------- helpers -----------------------------------------------------
__device__ __forceinline__ u32 smem_u32(const void* p) {
    u32 a;
    asm("{ .reg .u64 t; cvta.to.shared.u64 t, %1; cvt.u32.u64 %0, t; }" : "=r"(a) : "l"(p));
    return a;
}
__device__ __forceinline__ void mma_f16(float* d, u32 a0, u32 a1, u32 a2, u32 a3,
                                        u32 b0, u32 b1) {
    asm volatile(
        "mma.sync.aligned.m16n8k16.row.col.f32.f16.f16.f32 "
        "{%0,%1,%2,%3}, {%4,%5,%6,%7}, {%8,%9}, {%0,%1,%2,%3};"
        : "+f"(d[0]), "+f"(d[1]), "+f"(d[2]), "+f"(d[3])
        : "r"(a0), "r"(a1), "r"(a2), "r"(a3), "r"(b0), "r"(b1));
}
// 2 floats -> fp16x2 hi + fp16x2 residual lo
__device__ __forceinline__ void cvt_h2(float a, float b, u32& hi, u32& lo) {
    __half2 h = __floats2half2_rn(a, b);
    float ra = a - __half2float(__low2half(h));
    float rb = b - __half2float(__high2half(h));
    __half2 l = __floats2half2_rn(ra, rb);
    hi = *(u32*)&h; lo = *(u32*)&l;
}
__device__ __forceinline__ void cp16(u32 daddr, const void* gp, int zf) {
    asm volatile("cp.async.ca.shared.global [%0], [%1], 16, %2;"
                 :: "r"(daddr), "l"(gp), "r"(zf));
}
__device__ __forceinline__ void cp16f(u32 daddr, const void* gp) {
    asm volatile("cp.async.ca.shared.global [%0], [%1], 16;"
                 :: "r"(daddr), "l"(gp));
}

// ---------------- weight pre-conversion ---------------------------------------
__global__ void k_prep(const float* __restrict__ W0, const float* __restrict__ W1) {
    int idx = blockIdx.x * blockDim.x + threadIdx.x;
    if (idx < HID * KW) {
        int n = idx / KW, k = idx % KW;
        float w = (k < 2 * NG) ? W0[k * HID + n] : 0.f;
        g_W0h[idx] = __float2half(w);
    }
    if (idx < 1024 * HID) {
        int g = idx / HID, k = idx % HID;
        float wb = (g < NG) ? W1[k * 2 * NG + g] : 0.f;
        float wg = (g < NG) ? W1[k * 2 * NG + NG + g] : 0.f;
        g_Bb[idx] = __float2half(wb);
        g_Bg[idx] = __float2half(wg);
    }
}

// ---------------- degree count -------------------------------------------------
__global__ void k_count(const int* __restrict__ src, const int* __restrict__ dst, int E) {
    int e4 = (blockIdx.x * blockDim.x + threadIdx.x) * 4;
    if (e4 + 3 < E) {
        int4 s = *(const int4*)&src[e4];
        int4 d = *(const int4*)&dst[e4];
        atomicAdd(&g_deg_out[s.x], 1); atomicAdd(&g_deg_out[s.y], 1);
        atomicAdd(&g_deg_out[s.z], 1); atomicAdd(&g_deg_out[s.w], 1);
        atomicAdd(&g_deg_in[d.x], 1);  atomicAdd(&g_deg_in[d.y], 1);
        atomicAdd(&g_deg_in[d.z], 1);  atomicAdd(&g_deg_in[d.w], 1);
    } else {
        for (int e = e4; e < E; e++) {
            atomicAdd(&g_deg_out[src[e]], 1);
            atomicAdd(&g_deg_in[dst[e]], 1);
        }
    }
}

// ---------------- scan ----------------------------------------------------------
__global__ __launch_bounds__(1024) void k_scan1() {
    __shared__ int s[1024];
    int t = threadIdx.x;
    int i = blockIdx.x * 1024 + t;
    int v = (i < NN) ? g_deg_in[i] : 0;
    s[t] = v;
    __syncthreads();
    #pragma unroll
    for (int d = 1; d < 1024; d <<= 1) {
        int x = (t >= d) ? s[t - d] : 0;
        __syncthreads();
        s[t] += x;
        __syncthreads();
    }
    if (i < NN) g_offtmp[i] = s[t];
    if (t == 1023) g_bsum[blockIdx.x] = s[1023];
}

__global__ void k_scan2() {
    __shared__ int s[64];
    int t = threadIdx.x;
    int v = (t < NB) ? g_bsum[t] : 0;
    s[t] = v;
    __syncthreads();
    #pragma unroll
    for (int d = 1; d < 64; d <<= 1) {
        int x = (t >= d) ? s[t - d] : 0;
        __syncthreads();
        s[t] += x;
        __syncthreads();
    }
    if (t < NB) g_bpre[t] = s[t] - v;
}

__global__ __launch_bounds__(1024) void k_scan3() {
    int i = blockIdx.x * 1024 + threadIdx.x;
    if (i >= NN) return;
    int v = g_deg_in[i];
    int excl = g_offtmp[i] - v + g_bpre[blockIdx.x];
    g_off[i] = excl;
    if (i == NN - 1) g_off[NN] = excl + v;
    g_norm_dst[i] = rsqrtf(fmaxf((float)v, 1.0f));
    g_norm_src[i] = rsqrtf(fmaxf((float)g_deg_out[i], 1.0f));
}

// ---------------- CSR fill -------------------------------------------------------
__global__ void k_fill(const int* __restrict__ src, const int* __restrict__ dst, int E) {
    int e4 = (blockIdx.x * blockDim.x + threadIdx.x) * 4;
    if (e4 + 3 < E) {
        int4 s = *(const int4*)&src[e4];
        int4 d = *(const int4*)&dst[e4];
        g_csr[g_off[d.x] + atomicAdd(&g_ctr[d.x], 1)] = s.x;
        g_csr[g_off[d.y] + atomicAdd(&g_ctr[d.y], 1)] = s.y;
        g_csr[g_off[d.z] + atomicAdd(&g_ctr[d.z], 1)] = s.z;
        g_csr[g_off[d.w] + atomicAdd(&g_ctr[d.w], 1)] = s.w;
    } else {
        for (int e = e4; e < E; e++) {
            int d = dst[e];
            g_csr[g_off[d] + atomicAdd(&g_ctr[d], 1)] = src[e];
        }
    }
}

// ---------------- GEMM1: g_t = concat(xu,xs) @ W0 (unscaled) --------------------
// fp16 2-term: A split hi/lo, B single fp16
#define G1_SMEM (2 * 128 * APAD * 4 + 2 * 64 * KPAD * 2)
__global__ __launch_bounds__(256, 2) void k_gemm1(
    const float* __restrict__ xu, const float* __restrict__ xs) {
    extern __shared__ __align__(16) char sm[];
    float* Af = (float*)sm;                                  // [2][128][APAD]
    __half* Bsm = (__half*)(sm + 2 * 128 * APAD * 4);        // [2][64][KPAD]
    u32 aBase = smem_u32(sm);
    u32 bBase = aBase + 2 * 128 * APAD * 4;

    int tid = threadIdx.x, warp = tid >> 5, lane = tid & 31;
    int grp = lane >> 2, tig = lane & 3;
    int i0 = blockIdx.x * 128, m0 = warp * 16;

    float acc[8][4];
    #pragma unroll
    for (int n = 0; n < 8; n++)
        #pragma unroll
        for (int j = 0; j < 4; j++) acc[n][j] = 0.f;

    auto loadA = [&](int c) {
        int kb = c * 64;
        u32 da = aBase + (u32)(c & 1) * 128 * APAD * 4;
        #pragma unroll
        for (int q = 0; q < 8; q++) {
            int idx = q * 256 + tid;
            int r = idx >> 4, kq = (idx & 15) << 2;
            int i = i0 + r, k = kb + kq;
            const float* gp = xu;
            int zf = 0;
            if (i < NN && k < 2 * NG) {
                gp = (k < NG) ? xu + (size_t)i * NG + k
                              : xs + (size_t)i * NG + (k - NG);
                zf = 16;
            }
            cp16(da + (r * APAD + kq) * 4, gp, zf);
        }
        u32 db = bBase + (u32)(c & 1) * (64 * KPAD * 2);
        #pragma unroll
        for (int q = 0; q < 2; q++) {
            int idx = q * 256 + tid;          // 512 granules
            int n = idx >> 3, kq = (idx & 7) << 3;
            cp16f(db + (n * KPAD + kq) * 2, g_W0h + n * KW + kb + kq);
        }
        asm volatile("cp.async.commit_group;" ::: "memory");
    };

    loadA(0);
    for (int c = 0; c < 32; c++) {
        if (c < 31) {
            loadA(c + 1);
            asm volatile("cp.async.wait_group 1;" ::: "memory");
        } else {
            asm volatile("cp.async.wait_group 0;" ::: "memory");
        }
        __syncthreads();

        const float* A = Af + (c & 1) * 128 * APAD;
        const __half* Bh = Bsm + (c & 1) * 64 * KPAD;

        #pragma unroll
        for (int ks = 0; ks < 4; ks++) {
            int k0 = ks * 16;
            float2 f0 = *(const float2*)&A[(m0 + grp) * APAD + k0 + 2 * tig];
            float2 f1 = *(const float2*)&A[(m0 + grp + 8) * APAD + k0 + 2 * tig];
            float2 f2 = *(const float2*)&A[(m0 + grp) * APAD + k0 + 2 * tig + 8];
            float2 f3 = *(const float2*)&A[(m0 + grp + 8) * APAD + k0 + 2 * tig + 8];
            u32 ah0, al0, ah1, al1, ah2, al2, ah3, al3;
            cvt_h2(f0.x, f0.y, ah0, al0);
            cvt_h2(f1.x, f1.y, ah1, al1);
            cvt_h2(f2.x, f2.y, ah2, al2);
            cvt_h2(f3.x, f3.y, ah3, al3);
            #pragma unroll
            for (int n = 0; n < 8; n++) {
                int nb = n * 8 + grp;
                u32 bh0 = *(const u32*)&Bh[nb * KPAD + k0 + 2 * tig];
                u32 bh1 = *(const u32*)&Bh[nb * KPAD + k0 + 2 * tig + 8];
                mma_f16(acc[n], ah0, ah1, ah2, ah3, bh0, bh1);
                mma_f16(acc[n], al0, al1, al2, al3, bh0, bh1);
            }
        }
        __syncthreads();
    }

    int r0 = i0 + m0 + grp;
    int r1 = r0 + 8;
    #pragma unroll
    for (int n = 0; n < 8; n++) {
        int col = n * 8 + tig * 2;
        if (r0 < NN)
            *(float2*)&g_t[(size_t)r0 * HID + col] = make_float2(acc[n][0], acc[n][1]);
        if (r1 < NN)
            *(float2*)&g_t[(size_t)r1 * HID + col] = make_float2(acc[n][2], acc[n][3]);
    }
}

// ---------------- CSR gather: warp per node --------------------------------------
template <int MODE>
__global__ __launch_bounds__(256) void k_gather(const float* __restrict__ t,
                                                const float* __restrict__ b0,
                                                float* __restrict__ o) {
    int gw = (blockIdx.x * 256 + threadIdx.x) >> 5;
    if (gw >= NN) return;
    int lane = threadIdx.x & 31;
    int beg = g_off[gw], end = g_off[gw + 1];

    float2 acc = make_float2(0.f, 0.f);
    int j = beg;
    for (; j + 4 <= end; j += 4) {
        int s0 = g_csr[j], s1 = g_csr[j + 1], s2 = g_csr[j + 2], s3 = g_csr[j + 3];
        float2 v0 = *(const float2*)&t[(size_t)s0 * HID + 2 * lane];
        float2 v1 = *(const float2*)&t[(size_t)s1 * HID + 2 * lane];
        float2 v2 = *(const float2*)&t[(size_t)s2 * HID + 2 * lane];
        float2 v3 = *(const float2*)&t[(size_t)s3 * HID + 2 * lane];
        if (MODE == 0) {
            float n0 = g_norm_src[s0], n1 = g_norm_src[s1];
            float n2 = g_norm_src[s2], n3 = g_norm_src[s3];
            acc.x = fmaf(v0.x, n0, fmaf(v1.x, n1, fmaf(v2.x, n2, fmaf(v3.x, n3, acc.x))));
            acc.y = fmaf(v0.y, n0, fmaf(v1.y, n1, fmaf(v2.y, n2, fmaf(v3.y, n3, acc.y))));
        } else {
            acc.x += v0.x + v1.x + v2.x + v3.x;
            acc.y += v0.y + v1.y + v2.y + v3.y;
        }
    }
    for (; j < end; j++) {
        int s = g_csr[j];
        float2 v = *(const float2*)&t[(size_t)s * HID + 2 * lane];
        if (MODE == 0) {
            float ns = g_norm_src[s];
            acc.x = fmaf(v.x, ns, acc.x);
            acc.y = fmaf(v.y, ns, acc.y);
        } else {
            acc.x += v.x; acc.y += v.y;
        }
    }

    float nd = g_norm_dst[gw];
    float2 r;
    if (MODE == 0) {
        float ns = g_norm_src[gw];
        float2 b = *(const float2*)&b0[2 * lane];
        r.x = fmaxf(fmaf(acc.x, nd, b.x), 0.f) * ns;
        r.y = fmaxf(fmaf(acc.y, nd, b.y), 0.f) * ns;
    } else {
        r.x = acc.x * nd;
        r.y = acc.y * nd;
    }
    *(float2*)&o[(size_t)gw * HID + 2 * lane] = r;
}

// ---------------- fused GEMM2 + epilogue ------------------------------------------
#define KO_SMEM (128 * APAD * 4 + 2 * 64 * KPAD * 2)
__global__ __launch_bounds__(256) void k_out(
    const float* __restrict__ xu, const float* __restrict__ xs,
    const float* __restrict__ b1, float* __restrict__ out) {
    extern __shared__ __align__(16) char sm[];
    float* Zf = (float*)sm;                                  // [128][APAD]
    __half* Bsm = (__half*)(sm + 128 * APAD * 4);            // [2][64][KPAD]
    u32 zBase = smem_u32(sm);
    u32 bBase = zBase + 128 * APAD * 4;

    int tid = threadIdx.x, warp = tid >> 5, lane = tid & 31;
    int grp = lane >> 2, tig = lane & 3;
    int i0 = blockIdx.y * 128;
    int g0 = blockIdx.x * 64;
    int m0 = warp * 16;

    #pragma unroll
    for (int q = 0; q < 8; q++) {
        int idx = q * 256 + tid;
        int r = idx >> 4, kq = (idx & 15) << 2;
        int i = i0 + r;
        const float* gp = g_z;
        int zf = 0;
        if (i < NN) { gp = g_z + (size_t)i * HID + kq; zf = 16; }
        cp16(zBase + (r * APAD + kq) * 4, gp, zf);
    }
    #pragma unroll
    for (int q = 0; q < 4; q++) {
        int idx = q * 256 + tid;          // 1024 granules
        int arr = idx >> 9;               // 0:beta 1:gamma
        int rem = idx & 511;
        int n = rem >> 3, kq = (rem & 7) << 3;
        const __half* base = arr ? g_Bg : g_Bb;
        cp16f(bBase + arr * (64 * KPAD * 2) + (n * KPAD + kq) * 2,
              base + (g0 + n) * HID + kq);
    }
    asm volatile("cp.async.commit_group;" ::: "memory");
    asm volatile("cp.async.wait_group 0;" ::: "memory");
    __syncthreads();

    const __half* Bb = Bsm;
    const __half* Bg = Bsm + 64 * KPAD;

    float aB[8][4], aG[8][4];
    #pragma unroll
    for (int n = 0; n < 8; n++)
        #pragma unroll
        for (int j = 0; j < 4; j++) { aB[n][j] = 0.f; aG[n][j] = 0.f; }

    #pragma unroll
    for (int ks = 0; ks < 4; ks++) {
        int k0 = ks * 16;
        float2 f0 = *(const float2*)&Zf[(m0 + grp) * APAD + k0 + 2 * tig];
        float2 f1 = *(const float2*)&Zf[(m0 + grp + 8) * APAD + k0 + 2 * tig];
        float2 f2 = *(const float2*)&Zf[(m0 + grp) * APAD + k0 + 2 * tig + 8];
        float2 f3 = *(const float2*)&Zf[(m0 + grp + 8) * APAD + k0 + 2 * tig + 8];
        u32 ah0, al0, ah1, al1, ah2, al2, ah3, al3;
        cvt_h2(f0.x, f0.y, ah0, al0);
        cvt_h2(f1.x, f1.y, ah1, al1);
        cvt_h2(f2.x, f2.y, ah2, al2);
        cvt_h2(f3.x, f3.y, ah3, al3);
        #pragma unroll
        for (int n = 0; n < 8; n++) {
            int nb = n * 8 + grp;
            u32 b0r = *(const u32*)&Bb[nb * KPAD + k0 + 2 * tig];
            u32 b1r = *(const u32*)&Bb[nb * KPAD + k0 + 2 * tig + 8];
            mma_f16(aB[n], ah0, ah1, ah2, ah3, b0r, b1r);
            mma_f16(aB[n], al0, al1, al2, al3, b0r, b1r);
            u32 g0r = *(const u32*)&Bg[nb * KPAD + k0 + 2 * tig];
            u32 g1r = *(const u32*)&Bg[nb * KPAD + k0 + 2 * tig + 8];
            mma_f16(aG[n], ah0, ah1, ah2, ah3, g0r, g1r);
            mma_f16(aG[n], al0, al1, al2, al3, g0r, g1r);
        }
    }

    int r0 = i0 + m0 + grp;
    int r1 = r0 + 8;
    #pragma unroll
    for (int n = 0; n < 8; n++) {
        int gene = g0 + n * 8 + tig * 2;
        if (gene >= NG) continue;
        float2 bb = *(const float2*)&b1[gene];
        float2 bg = *(const float2*)&b1[NG + gene];
        if (r0 < NN) {
            float2 u = *(const float2*)&xu[(size_t)r0 * NG + gene];
            float2 s = *(const float2*)&xs[(size_t)r0 * NG + gene];
            float2 o;
            o.x = (aB[n][0] + bb.x) * u.x + (aG[n][0] + bg.x) * s.x;
            o.y = (aB[n][1] + bb.y) * u.y + (aG[n][1] + bg.y) * s.y;
            *(float2*)&out[(size_t)r0 * NG + gene] = o;
        }
        if (r1 < NN) {
            float2 u = *(const float2*)&xu[(size_t)r1 * NG + gene];
            float2 s = *(const float2*)&xs[(size_t)r1 * NG + gene];
            float2 o;
            o.x = (aB[n][2] + bb.x) * u.x + (aG[n][2] + bg.x) * s.x;
            o.y = (aB[n][3] + bb.y) * u.y + (aG[n][3] + bg.y) * s.y;
            *(float2*)&out[(size_t)r1 * NG + gene] = o;
        }
    }
}

// ---------------- host launcher ---------------------------------------------------
extern "C" void kernel_launch(void* const* d_in, const int* in_sizes, int n_in,
                              void* d_out, int out_size) {
    const float* xu = (const float*)d_in[0];
    const float* xs = (const float*)d_in[1];
    const float* W0 = (const float*)d_in[2];
    const float* b0 = (const float*)d_in[3];
    const float* W1 = (const float*)d_in[4];
    const float* b1 = (const float*)d_in[5];
    const int* src = (const int*)d_in[6];
    const int* dst = (const int*)d_in[7];
    int E = in_sizes[6];
    float* out = (float*)d_out;

    void *p_degi, *p_dego, *p_ctr, *p_t, *p_hs, *p_z;
    cudaGetSymbolAddress(&p_degi, g_deg_in);
    cudaGetSymbolAddress(&p_dego, g_deg_out);
    cudaGetSymbolAddress(&p_ctr, g_ctr);
    cudaGetSymbolAddress(&p_t, g_t);
    cudaGetSymbolAddress(&p_hs, g_hs);
    cudaGetSymbolAddress(&p_z, g_z);

    static cudaStream_t s1 = nullptr;
    static cudaEvent_t evFork = nullptr, evJoin = nullptr;
    static int attr_done = 0;
    if (!attr_done) {
        cudaFuncSetAttribute(k_gemm1, cudaFuncAttributeMaxDynamicSharedMemorySize, G1_SMEM);
        cudaFuncSetAttribute(k_out, cudaFuncAttributeMaxDynamicSharedMemorySize, KO_SMEM);
        cudaStreamCreateWithFlags(&s1, cudaStreamNonBlocking);
        cudaEventCreateWithFlags(&evFork, cudaEventDisableTiming);
        cudaEventCreateWithFlags(&evJoin, cudaEventDisableTiming);
        attr_done = 1;
    }

    cudaEventRecord(evFork, 0);
    cudaStreamWaitEvent(s1, evFork, 0);

    // chain B: CSR build
    cudaMemsetAsync(p_degi, 0, NN * sizeof(int), s1);
    cudaMemsetAsync(p_dego, 0, NN * sizeof(int), s1);
    cudaMemsetAsync(p_ctr, 0, NN * sizeof(int), s1);
    k_count<<<(E / 4 + 255) / 256, 256, 0, s1>>>(src, dst, E);
    k_scan1<<<NB, 1024, 0, s1>>>();
    k_scan2<<<1, 64, 0, s1>>>();
    k_scan3<<<NB, 1024, 0, s1>>>();
    k_fill<<<(E / 4 + 255) / 256, 256, 0, s1>>>(src, dst, E);
    cudaEventRecord(evJoin, s1);

    // chain A: weights + GEMM1
    k_prep<<<(HID * KW + 255) / 256, 256>>>(W0, W1);
    k_gemm1<<<(NN + 127) / 128, 256, G1_SMEM>>>(xu, xs);

    cudaStreamWaitEvent(0, evJoin, 0);

    k_gather<0><<<(NN * 32 + 255) / 256, 256>>>((const float*)p_t, b0, (float*)p_hs);
    k_gather<1><<<(NN * 32 + 255) / 256, 256>>>((const float*)p_hs, b0, (float*)p_z);
    k_out<<<dim3(16, (NN + 127) / 128), 256, KO_SMEM>>>(xu, xs, b1, out);
}